// round 13
// baseline (speedup 1.0000x reference)
#include <cuda_runtime.h>
#include <math.h>

#define TT 2048
#define CC 1024
#define HH 16
#define DD 64
#define EE 8
#define FF 4096

// ---------------- scratch (static device globals; no allocation) ----------------
__device__ float g_xn [TT*CC];
__device__ float g_xn2[TT*CC];
__device__ float g_att[TT*CC];
__device__ float g_q[HH*TT*DD];
__device__ float g_k[HH*TT*DD];
__device__ float g_v[HH*TT*DD];
__device__ float g_gate[TT*EE];
__device__ int   g_list [EE*TT];
__device__ float g_lgate[EE*TT];
__device__ int   g_count[EE];
__device__ float g_h[TT*FF];

// ---------------- tf32 helpers ----------------
__device__ __forceinline__ unsigned f2tf(float f) {
    unsigned u;
    asm("cvt.rna.tf32.f32 %0, %1;" : "=r"(u) : "f"(f));
    return u;
}
__device__ __forceinline__ void cvt4(unsigned* dst, float4 v) {
    dst[0] = f2tf(v.x); dst[1] = f2tf(v.y); dst[2] = f2tf(v.z); dst[3] = f2tf(v.w);
}
// split: hi = tf32(x), lo = tf32(x - hi)
__device__ __forceinline__ void split4(unsigned* hi, unsigned* lo, float4 v) {
    float f[4] = {v.x, v.y, v.z, v.w};
#pragma unroll
    for (int i = 0; i < 4; i++) {
        unsigned h = f2tf(f[i]);
        hi[i] = h;
        float hf = __uint_as_float(h);
        lo[i] = f2tf(f[i] - hf);
    }
}
__device__ __forceinline__ void split1(unsigned& hi, unsigned& lo, float f) {
    hi = f2tf(f);
    lo = f2tf(f - __uint_as_float(hi));
}
__device__ __forceinline__ void mma_tf32(float* c, const unsigned* a, const unsigned* b) {
    asm volatile("mma.sync.aligned.m16n8k8.row.col.f32.tf32.tf32.f32 "
                 "{%0,%1,%2,%3},{%4,%5,%6,%7},{%8,%9},{%0,%1,%2,%3};"
                 : "+f"(c[0]), "+f"(c[1]), "+f"(c[2]), "+f"(c[3])
                 : "r"(a[0]), "r"(a[1]), "r"(a[2]), "r"(a[3]),
                   "r"(b[0]), "r"(b[1]));
}

#define AP 36    // As row stride, 32-K-chunk kernels
#define BP 72    // Bs row stride
#define AP2 20   // As row stride, 16-K-chunk 3x kernels

// ---- 1x tf32 chunk (K=32) ----
#define MMA_CHUNK(As, Bs, acc, wm, wn, g, t4)                                   \
    _Pragma("unroll")                                                           \
    for (int ks = 0; ks < 4; ks++) {                                            \
        int kb = ks * 8;                                                        \
        unsigned afr[2][4], bfr[4][2];                                          \
        _Pragma("unroll")                                                       \
        for (int mi = 0; mi < 2; mi++) {                                        \
            int r0 = (wm)*32 + mi*16 + (g);                                     \
            afr[mi][0] = As[r0  ][kb + (t4)];                                   \
            afr[mi][1] = As[r0+8][kb + (t4)];                                   \
            afr[mi][2] = As[r0  ][kb + 4 + (t4)];                               \
            afr[mi][3] = As[r0+8][kb + 4 + (t4)];                               \
        }                                                                       \
        _Pragma("unroll")                                                       \
        for (int ni = 0; ni < 4; ni++) {                                        \
            int c0 = (wn)*32 + ni*8 + (g);                                      \
            bfr[ni][0] = Bs[kb + (t4)    ][c0];                                 \
            bfr[ni][1] = Bs[kb + 4 + (t4)][c0];                                 \
        }                                                                       \
        _Pragma("unroll")                                                       \
        for (int mi = 0; mi < 2; mi++)                                          \
            _Pragma("unroll")                                                   \
            for (int ni = 0; ni < 4; ni++)                                      \
                mma_tf32(acc[mi][ni], afr[mi], bfr[ni]);                        \
    }

// ---- 3x tf32 chunk (K=16, hi/lo split operands) ----
#define MMA_CHUNK3(Ah, Al, Bh, Bl, acc, wm, wn, g, t4)                          \
    _Pragma("unroll")                                                           \
    for (int ks = 0; ks < 2; ks++) {                                            \
        int kb = ks * 8;                                                        \
        unsigned ah[2][4], al[2][4], bh[4][2], bl[4][2];                        \
        _Pragma("unroll")                                                       \
        for (int mi = 0; mi < 2; mi++) {                                        \
            int r0 = (wm)*32 + mi*16 + (g);                                     \
            ah[mi][0]=Ah[r0  ][kb+(t4)];   al[mi][0]=Al[r0  ][kb+(t4)];         \
            ah[mi][1]=Ah[r0+8][kb+(t4)];   al[mi][1]=Al[r0+8][kb+(t4)];         \
            ah[mi][2]=Ah[r0  ][kb+4+(t4)]; al[mi][2]=Al[r0  ][kb+4+(t4)];       \
            ah[mi][3]=Ah[r0+8][kb+4+(t4)]; al[mi][3]=Al[r0+8][kb+4+(t4)];       \
        }                                                                       \
        _Pragma("unroll")                                                       \
        for (int ni = 0; ni < 4; ni++) {                                        \
            int c0 = (wn)*32 + ni*8 + (g);                                      \
            bh[ni][0]=Bh[kb+(t4)  ][c0];   bl[ni][0]=Bl[kb+(t4)  ][c0];         \
            bh[ni][1]=Bh[kb+4+(t4)][c0];   bl[ni][1]=Bl[kb+4+(t4)][c0];         \
        }                                                                       \
        _Pragma("unroll")                                                       \
        for (int mi = 0; mi < 2; mi++)                                          \
            _Pragma("unroll")                                                   \
            for (int ni = 0; ni < 4; ni++) {                                    \
                mma_tf32(acc[mi][ni], ah[mi], bh[ni]);                          \
                mma_tf32(acc[mi][ni], ah[mi], bl[ni]);                          \
                mma_tf32(acc[mi][ni], al[mi], bh[ni]);                          \
            }                                                                   \
    }

// ---------------- LayerNorm ----------------
__global__ void ln_kernel(const float* __restrict__ x, const float* __restrict__ gw,
                          const float* __restrict__ bw, int which) {
    int t = blockIdx.x;
    int tid = threadIdx.x;
    const float* row = x + (size_t)t * CC;
    float vals[4];
    float s = 0.f, s2 = 0.f;
#pragma unroll
    for (int i = 0; i < 4; i++) {
        float v = row[tid + i * 256];
        vals[i] = v; s += v; s2 += v * v;
    }
#pragma unroll
    for (int o = 16; o > 0; o >>= 1) {
        s  += __shfl_xor_sync(0xffffffffu, s, o);
        s2 += __shfl_xor_sync(0xffffffffu, s2, o);
    }
    __shared__ float red[2][8];
    __shared__ float smean, srstd;
    if ((tid & 31) == 0) { red[0][tid >> 5] = s; red[1][tid >> 5] = s2; }
    __syncthreads();
    if (tid < 32) {
        float a  = (tid < 8) ? red[0][tid] : 0.f;
        float a2 = (tid < 8) ? red[1][tid] : 0.f;
#pragma unroll
        for (int o = 4; o > 0; o >>= 1) {
            a  += __shfl_xor_sync(0xffffffffu, a, o);
            a2 += __shfl_xor_sync(0xffffffffu, a2, o);
        }
        if (tid == 0) {
            float m = a * (1.f / CC);
            smean = m;
            srstd = rsqrtf(a2 * (1.f / CC) - m * m + 1e-5f);
        }
    }
    __syncthreads();
    float m = smean, r = srstd;
    float* orow = (which == 0 ? g_xn : g_xn2) + (size_t)t * CC;
#pragma unroll
    for (int i = 0; i < 4; i++) {
        int c = tid + i * 256;
        orow[c] = (vals[i] - m) * r * gw[c] + bw[c];
    }
}

// ---------------- QKV 3xTF32 GEMM: tile 128x64, K-chunk 16, grid (Mtiles, H) ----------------
__global__ __launch_bounds__(256, 2) void qkv_tc(const float* __restrict__ W, int which) {
    int h = blockIdx.y;
    int m0 = blockIdx.x * 128;
    const float* B = W + (size_t)h * CC * DD;
    float* O = (which == 0 ? g_q : which == 1 ? g_k : g_v) + (size_t)h * TT * DD;
    __shared__ unsigned Ah[128][AP2], Al[128][AP2];
    __shared__ unsigned Bh[16][BP],  Bl[16][BP];
    int tid = threadIdx.x, lane = tid & 31, warp = tid >> 5;
    int wm = warp >> 1, wn = warp & 1, g = lane >> 2, t4 = lane & 3;
    float acc[2][4][4] = {};
    for (int k0 = 0; k0 < CC; k0 += 16) {
        float4 av[2], bv;
#pragma unroll
        for (int i = 0; i < 2; i++) {
            int idx = tid + i * 256, r = idx >> 2, c4 = (idx & 3) * 4;
            av[i] = *(const float4*)(g_xn + (size_t)(m0 + r) * CC + k0 + c4);
        }
        {
            int r = tid >> 4, c4 = (tid & 15) * 4;
            bv = *(const float4*)(B + (size_t)(k0 + r) * DD + c4);
        }
        __syncthreads();
#pragma unroll
        for (int i = 0; i < 2; i++) {
            int idx = tid + i * 256, r = idx >> 2, c4 = (idx & 3) * 4;
            split4(&Ah[r][c4], &Al[r][c4], av[i]);
        }
        {
            int r = tid >> 4, c4 = (tid & 15) * 4;
            split4(&Bh[r][c4], &Bl[r][c4], bv);
        }
        __syncthreads();
        MMA_CHUNK3(Ah, Al, Bh, Bl, acc, wm, wn, g, t4)
    }
#pragma unroll
    for (int mi = 0; mi < 2; mi++)
#pragma unroll
        for (int ni = 0; ni < 4; ni++) {
            int row = m0 + wm*32 + mi*16 + g;
            int col = wn*32 + ni*8 + 2*t4;
            float* c = acc[mi][ni];
            *(float2*)(O + (size_t)row * DD + col)     = make_float2(c[0], c[1]);
            *(float2*)(O + (size_t)(row+8) * DD + col) = make_float2(c[2], c[3]);
        }
}

// ---------------- Flash attention, tensor-core 3xTF32 ----------------
// block: 128 Q rows x 1 head, 8 warps, warp = 16 rows x full tile width.
// Q in registers (pre-split A-fragments), K transposed [d][key], V [key][d] in smem.
__global__ __launch_bounds__(256) void attn_tc() {
    int h  = blockIdx.y;
    int mi = (TT / 128 - 1) - blockIdx.x;     // heavy blocks first
    int m0 = mi * 128;
    const float* Q = g_q + (size_t)h * TT * DD;
    const float* K = g_k + (size_t)h * TT * DD;
    const float* V = g_v + (size_t)h * TT * DD;
    __shared__ unsigned Kth[64][40], Ktl[64][40];   // K^T hi/lo: [d][key], pad 40
    __shared__ unsigned Vsh[32][72], Vsl[32][72];   // V hi/lo: [key][d],  pad 72
    int tid = threadIdx.x, lane = tid & 31, warp = tid >> 5;
    int g = lane >> 2, t4 = lane & 3;
    int qrow = m0 + warp * 16 + g;

    // Q A-fragments, pre-scaled by C^-0.5, hi/lo split
    unsigned qh[8][4], ql[8][4];
    const float sc = 0.03125f;
#pragma unroll
    for (int ks = 0; ks < 8; ks++) {
        int kb = ks * 8;
        float v0 = Q[(size_t)qrow * DD + kb + t4] * sc;
        float v1 = Q[(size_t)(qrow + 8) * DD + kb + t4] * sc;
        float v2 = Q[(size_t)qrow * DD + kb + 4 + t4] * sc;
        float v3 = Q[(size_t)(qrow + 8) * DD + kb + 4 + t4] * sc;
        split1(qh[ks][0], ql[ks][0], v0);
        split1(qh[ks][1], ql[ks][1], v1);
        split1(qh[ks][2], ql[ks][2], v2);
        split1(qh[ks][3], ql[ks][3], v3);
    }

    float o[8][4] = {};                 // O accum: 8 d-groups, C-layout frags
    float mrow0 = -INFINITY, mrow1 = -INFINITY;
    float lrow0 = 0.f, lrow1 = 0.f;
    int wr = m0 + warp * 16;

    int ntiles = (mi + 1) * 4;          // key tiles of 32
    for (int st = 0; st < ntiles; st++) {
        int s0 = st * 32;
        __syncthreads();
        // load K (transposed write) + V, hi/lo split
#pragma unroll
        for (int i = 0; i < 2; i++) {
            int idx = tid + i * 256;
            int r = idx >> 4, c4 = (idx & 15) * 4;
            float4 k4 = *(const float4*)(K + (size_t)(s0 + r) * DD + c4);
            float4 v4 = *(const float4*)(V + (size_t)(s0 + r) * DD + c4);
            float kf[4] = {k4.x, k4.y, k4.z, k4.w};
            float vf[4] = {v4.x, v4.y, v4.z, v4.w};
#pragma unroll
            for (int j = 0; j < 4; j++) {
                unsigned hk, lk, hv, lv;
                split1(hk, lk, kf[j]);
                split1(hv, lv, vf[j]);
                Kth[c4 + j][r] = hk; Ktl[c4 + j][r] = lk;
                Vsh[r][c4 + j] = hv; Vsl[r][c4 + j] = lv;
            }
        }
        __syncthreads();

        // S = Q @ K^T  (3x tf32)
        float sfr[4][4] = {};
#pragma unroll
        for (int ks = 0; ks < 8; ks++) {
            int kb = ks * 8;
#pragma unroll
            for (int ni = 0; ni < 4; ni++) {
                int c0 = ni * 8 + g;
                unsigned bh[2], bl[2];
                bh[0] = Kth[kb + t4][c0]; bh[1] = Kth[kb + 4 + t4][c0];
                bl[0] = Ktl[kb + t4][c0]; bl[1] = Ktl[kb + 4 + t4][c0];
                mma_tf32(sfr[ni], qh[ks], bh);
                mma_tf32(sfr[ni], qh[ks], bl);
                mma_tf32(sfr[ni], ql[ks], bh);
            }
        }

        // causal mask (only tiles overlapping the diagonal region of this warp)
        if (s0 + 31 > wr) {
#pragma unroll
            for (int ni = 0; ni < 4; ni++) {
                int c = s0 + ni * 8 + 2 * t4;
                if (c     > qrow)     sfr[ni][0] = -INFINITY;
                if (c + 1 > qrow)     sfr[ni][1] = -INFINITY;
                if (c     > qrow + 8) sfr[ni][2] = -INFINITY;
                if (c + 1 > qrow + 8) sfr[ni][3] = -INFINITY;
            }
        }

        // online softmax (rows g and g+8; quad-local reduction)
        float tmax0 = -INFINITY, tmax1 = -INFINITY;
#pragma unroll
        for (int ni = 0; ni < 4; ni++) {
            tmax0 = fmaxf(tmax0, fmaxf(sfr[ni][0], sfr[ni][1]));
            tmax1 = fmaxf(tmax1, fmaxf(sfr[ni][2], sfr[ni][3]));
        }
        tmax0 = fmaxf(tmax0, __shfl_xor_sync(0xffffffffu, tmax0, 1));
        tmax0 = fmaxf(tmax0, __shfl_xor_sync(0xffffffffu, tmax0, 2));
        tmax1 = fmaxf(tmax1, __shfl_xor_sync(0xffffffffu, tmax1, 1));
        tmax1 = fmaxf(tmax1, __shfl_xor_sync(0xffffffffu, tmax1, 2));
        float mn0 = fmaxf(mrow0, tmax0), mn1 = fmaxf(mrow1, tmax1);
        float cor0 = __expf(mrow0 - mn0), cor1 = __expf(mrow1 - mn1);
        mrow0 = mn0; mrow1 = mn1;
        float rs0 = 0.f, rs1 = 0.f;
#pragma unroll
        for (int ni = 0; ni < 4; ni++) {
            sfr[ni][0] = __expf(sfr[ni][0] - mn0);
            sfr[ni][1] = __expf(sfr[ni][1] - mn0);
            sfr[ni][2] = __expf(sfr[ni][2] - mn1);
            sfr[ni][3] = __expf(sfr[ni][3] - mn1);
            rs0 += sfr[ni][0] + sfr[ni][1];
            rs1 += sfr[ni][2] + sfr[ni][3];
        }
        rs0 += __shfl_xor_sync(0xffffffffu, rs0, 1);
        rs0 += __shfl_xor_sync(0xffffffffu, rs0, 2);
        rs1 += __shfl_xor_sync(0xffffffffu, rs1, 1);
        rs1 += __shfl_xor_sync(0xffffffffu, rs1, 2);
        lrow0 = lrow0 * cor0 + rs0;
        lrow1 = lrow1 * cor1 + rs1;
#pragma unroll
        for (int ni = 0; ni < 8; ni++) {
            o[ni][0] *= cor0; o[ni][1] *= cor0;
            o[ni][2] *= cor1; o[ni][3] *= cor1;
        }

        // P (C-layout) -> A-fragment via intra-quad shfl, then O += P @ V (3x tf32)
        int srcA = (lane & ~3) | (t4 >> 1);
        int srcB = srcA + 2;
        bool odd = (t4 & 1);
#pragma unroll
        for (int ks = 0; ks < 4; ks++) {
            float x0 = sfr[ks][0], x1 = sfr[ks][1], x2 = sfr[ks][2], x3 = sfr[ks][3];
            float yA0 = __shfl_sync(0xffffffffu, x0, srcA);
            float yA1 = __shfl_sync(0xffffffffu, x1, srcA);
            float yA2 = __shfl_sync(0xffffffffu, x2, srcA);
            float yA3 = __shfl_sync(0xffffffffu, x3, srcA);
            float yB0 = __shfl_sync(0xffffffffu, x0, srcB);
            float yB1 = __shfl_sync(0xffffffffu, x1, srcB);
            float yB2 = __shfl_sync(0xffffffffu, x2, srcB);
            float yB3 = __shfl_sync(0xffffffffu, x3, srcB);
            float p0 = odd ? yA1 : yA0;   // (row g,   k t4)
            float p1 = odd ? yA3 : yA2;   // (row g+8, k t4)
            float p2 = odd ? yB1 : yB0;   // (row g,   k t4+4)
            float p3 = odd ? yB3 : yB2;   // (row g+8, k t4+4)
            unsigned pah[4], pal[4];
            split1(pah[0], pal[0], p0);
            split1(pah[1], pal[1], p1);
            split1(pah[2], pal[2], p2);
            split1(pah[3], pal[3], p3);
            int kb = ks * 8;
#pragma unroll
            for (int ni = 0; ni < 8; ni++) {
                int c0 = ni * 8 + g;
                unsigned bh[2], bl[2];
                bh[0] = Vsh[kb + t4][c0]; bh[1] = Vsh[kb + 4 + t4][c0];
                bl[0] = Vsl[kb + t4][c0]; bl[1] = Vsl[kb + 4 + t4][c0];
                mma_tf32(o[ni], pah, bh);
                mma_tf32(o[ni], pah, bl);
                mma_tf32(o[ni], pal, bh);
            }
        }
    }

    float inv0 = 1.f / lrow0, inv1 = 1.f / lrow1;
#pragma unroll
    for (int ni = 0; ni < 8; ni++) {
        int col = h * DD + ni * 8 + 2 * t4;
        *(float2*)(g_att + (size_t)qrow * CC + col) =
            make_float2(o[ni][0] * inv0, o[ni][1] * inv0);
        *(float2*)(g_att + (size_t)(qrow + 8) * CC + col) =
            make_float2(o[ni][2] * inv1, o[ni][3] * inv1);
    }
}

// ---------------- proj 3xTF32 GEMM + bias + residual ----------------
__global__ __launch_bounds__(256, 2) void proj_tc(const float* __restrict__ W, const float* __restrict__ bias,
                         const float* __restrict__ xres, float* __restrict__ out) {
    int m0 = blockIdx.y * 128, n0 = blockIdx.x * 64;
    __shared__ unsigned Ah[128][AP2], Al[128][AP2];
    __shared__ unsigned Bh[16][BP],  Bl[16][BP];
    int tid = threadIdx.x, lane = tid & 31, warp = tid >> 5;
    int wm = warp >> 1, wn = warp & 1, g = lane >> 2, t4 = lane & 3;
    float acc[2][4][4] = {};
    for (int k0 = 0; k0 < CC; k0 += 16) {
        float4 av[2], bv;
#pragma unroll
        for (int i = 0; i < 2; i++) {
            int idx = tid + i * 256, r = idx >> 2, c4 = (idx & 3) * 4;
            av[i] = *(const float4*)(g_att + (size_t)(m0 + r) * CC + k0 + c4);
        }
        {
            int r = tid >> 4, c4 = (tid & 15) * 4;
            bv = *(const float4*)(W + (size_t)(k0 + r) * CC + n0 + c4);
        }
        __syncthreads();
#pragma unroll
        for (int i = 0; i < 2; i++) {
            int idx = tid + i * 256, r = idx >> 2, c4 = (idx & 3) * 4;
            split4(&Ah[r][c4], &Al[r][c4], av[i]);
        }
        {
            int r = tid >> 4, c4 = (tid & 15) * 4;
            split4(&Bh[r][c4], &Bl[r][c4], bv);
        }
        __syncthreads();
        MMA_CHUNK3(Ah, Al, Bh, Bl, acc, wm, wn, g, t4)
    }
#pragma unroll
    for (int mi = 0; mi < 2; mi++)
#pragma unroll
        for (int ni = 0; ni < 4; ni++) {
            int row = m0 + wm*32 + mi*16 + g;
            int col = n0 + wn*32 + ni*8 + 2*t4;
            float* c = acc[mi][ni];
            float2 bb = *(const float2*)(bias + col);
#pragma unroll
            for (int rr = 0; rr < 2; rr++) {
                size_t idx = (size_t)(row + rr*8) * CC + col;
                float2 xr = *(const float2*)(xres + idx);
                *(float2*)(out + idx) = make_float2(xr.x + c[rr*2+0] + bb.x,
                                                    xr.y + c[rr*2+1] + bb.y);
            }
        }
}

// ---------------- router: noisy top-2 gate (fp32) ----------------
__global__ void router_kernel(const float* __restrict__ Wr, const float* __restrict__ br,
                              const float* __restrict__ Wn, const float* __restrict__ bn,
                              const float* __restrict__ noise) {
    int t = blockIdx.x;
    int tid = threadIdx.x, e = tid >> 5, lane = tid & 31;
    const float* xr = g_xn2 + (size_t)t * CC;
    float sl = 0.f, sn = 0.f;
    for (int c = lane; c < CC; c += 32) {
        float xv = xr[c];
        sl += xv * Wr[c * EE + e];
        sn += xv * Wn[c * EE + e];
    }
#pragma unroll
    for (int o = 16; o > 0; o >>= 1) {
        sl += __shfl_xor_sync(0xffffffffu, sl, o);
        sn += __shfl_xor_sync(0xffffffffu, sn, o);
    }
    __shared__ float s_noisy[EE];
    if (lane == 0) {
        float lg = sl + br[e];
        float nl = sn + bn[e];
        float sp = (nl > 20.f) ? nl : log1pf(expf(nl));
        s_noisy[e] = lg + noise[(size_t)t * EE + e] * sp;
    }
    __syncthreads();
    if (tid == 0) {
        float n[EE];
#pragma unroll
        for (int i = 0; i < EE; i++) n[i] = s_noisy[i];
        int i1 = 0;
        for (int i = 1; i < EE; i++) if (n[i] > n[i1]) i1 = i;
        int i2 = -1;
        for (int i = 0; i < EE; i++) {
            if (i == i1) continue;
            if (i2 < 0 || n[i] > n[i2]) i2 = i;
        }
        float mx = fmaxf(n[i1], n[i2]);
        float e1 = __expf(n[i1] - mx), e2 = __expf(n[i2] - mx);
        float inv = 1.f / (e1 + e2);
#pragma unroll
        for (int i = 0; i < EE; i++) g_gate[(size_t)t * EE + i] = 0.f;
        g_gate[(size_t)t * EE + i1] = e1 * inv;
        g_gate[(size_t)t * EE + i2] = e2 * inv;
    }
}

// ---------------- deterministic per-expert token lists ----------------
__global__ void build_lists() {
    int e = threadIdx.x >> 5, lane = threadIdx.x & 31;
    int cnt = 0;
    for (int base = 0; base < TT; base += 32) {
        int t = base + lane;
        float gv = g_gate[(size_t)t * EE + e];
        unsigned mask = __ballot_sync(0xffffffffu, gv > 0.f);
        if (gv > 0.f) {
            int pos = cnt + __popc(mask & ((1u << lane) - 1u));
            g_list [e * TT + pos] = t;
            g_lgate[e * TT + pos] = gv;
        }
        cnt += __popc(mask);
    }
    if (lane == 0) g_count[e] = cnt;
}

// ---------------- MoE layer 1 (1xTF32, gathered A): h = relu(xn2[list]@W1[e] + b1) ----------------
__global__ __launch_bounds__(256, 2) void moe1_tc(const float* __restrict__ W1, const float* __restrict__ b1, int e) {
    int Ne = g_count[e];
    int m0 = blockIdx.y * 128;
    if (m0 >= Ne) return;
    int n0 = blockIdx.x * 64;
    const float* B = W1 + (size_t)e * CC * FF;
    const float* bias = b1 + (size_t)e * FF;
    __shared__ unsigned As[128][AP];
    __shared__ unsigned Bs[32][BP];
    __shared__ int rows[128];
    int tid = threadIdx.x, lane = tid & 31, warp = tid >> 5;
    int wm = warp >> 1, wn = warp & 1, g = lane >> 2, t4 = lane & 3;
    if (tid < 128) rows[tid] = (m0 + tid < Ne) ? g_list[e * TT + m0 + tid] : 0;
    __syncthreads();
    float acc[2][4][4] = {};
    for (int k0 = 0; k0 < CC; k0 += 32) {
        float4 av[4], bv[2];
#pragma unroll
        for (int i = 0; i < 4; i++) {
            int idx = tid + i * 256, r = idx >> 3, c4 = (idx & 7) * 4;
            av[i] = *(const float4*)(g_xn2 + (size_t)rows[r] * CC + k0 + c4);
        }
#pragma unroll
        for (int i = 0; i < 2; i++) {
            int idx = tid + i * 256, r = idx >> 4, c4 = (idx & 15) * 4;
            bv[i] = *(const float4*)(B + (size_t)(k0 + r) * FF + n0 + c4);
        }
        __syncthreads();
#pragma unroll
        for (int i = 0; i < 4; i++) {
            int idx = tid + i * 256, r = idx >> 3, c4 = (idx & 7) * 4;
            cvt4(&As[r][c4], av[i]);
        }
#pragma unroll
        for (int i = 0; i < 2; i++) {
            int idx = tid + i * 256, r = idx >> 4, c4 = (idx & 15) * 4;
            cvt4(&Bs[r][c4], bv[i]);
        }
        __syncthreads();
        MMA_CHUNK(As, Bs, acc, wm, wn, g, t4)
    }
#pragma unroll
    for (int mi = 0; mi < 2; mi++)
#pragma unroll
        for (int ni = 0; ni < 4; ni++) {
            int row = m0 + wm*32 + mi*16 + g;
            int col = n0 + wn*32 + ni*8 + 2*t4;
            float* c = acc[mi][ni];
            float2 bb = *(const float2*)(bias + col);
#pragma unroll
            for (int rr = 0; rr < 2; rr++) {
                int m = row + rr*8;
                if (m < Ne)
                    *(float2*)(g_h + (size_t)m * FF + col) =
                        make_float2(fmaxf(c[rr*2+0] + bb.x, 0.f),
                                    fmaxf(c[rr*2+1] + bb.y, 0.f));
            }
        }
}

// ---------------- MoE layer 2 (1xTF32): out[tok] += gate * (h@W2[e] + b2) ----------------
__global__ __launch_bounds__(256, 2) void moe2_tc(const float* __restrict__ W2, const float* __restrict__ b2,
                         float* __restrict__ out, int e) {
    int Ne = g_count[e];
    int m0 = blockIdx.y * 128;
    if (m0 >= Ne) return;
    int n0 = blockIdx.x * 64;
    const float* B = W2 + (size_t)e * FF * CC;
    const float* bias = b2 + (size_t)e * CC;
    __shared__ unsigned As[128][AP];
    __shared__ unsigned Bs[32][BP];
    int tid = threadIdx.x, lane = tid & 31, warp = tid >> 5;
    int wm = warp >> 1, wn = warp & 1, g = lane >> 2, t4 = lane & 3;
    float acc[2][4][4] = {};
    for (int k0 = 0; k0 < FF; k0 += 32) {
        float4 av[4], bv[2];
#pragma unroll
        for (int i = 0; i < 4; i++) {
            int idx = tid + i * 256, r = idx >> 3, c4 = (idx & 7) * 4;
            av[i] = *(const float4*)(g_h + (size_t)(m0 + r) * FF + k0 + c4);
        }
#pragma unroll
        for (int i = 0; i < 2; i++) {
            int idx = tid + i * 256, r = idx >> 4, c4 = (idx & 15) * 4;
            bv[i] = *(const float4*)(B + (size_t)(k0 + r) * CC + n0 + c4);
        }
        __syncthreads();
#pragma unroll
        for (int i = 0; i < 4; i++) {
            int idx = tid + i * 256, r = idx >> 3, c4 = (idx & 7) * 4;
            cvt4(&As[r][c4], av[i]);
        }
#pragma unroll
        for (int i = 0; i < 2; i++) {
            int idx = tid + i * 256, r = idx >> 4, c4 = (idx & 15) * 4;
            cvt4(&Bs[r][c4], bv[i]);
        }
        __syncthreads();
        MMA_CHUNK(As, Bs, acc, wm, wn, g, t4)
    }
#pragma unroll
    for (int mi = 0; mi < 2; mi++)
#pragma unroll
        for (int ni = 0; ni < 4; ni++) {
            int row = m0 + wm*32 + mi*16 + g;
            int col = n0 + wn*32 + ni*8 + 2*t4;
            float* c = acc[mi][ni];
            float2 bb = *(const float2*)(bias + col);
#pragma unroll
            for (int rr = 0; rr < 2; rr++) {
                int m = row + rr*8;
                if (m < Ne) {
                    int tok = g_list[e * TT + m];
                    float gv = g_lgate[e * TT + m];
                    float2* op = (float2*)(out + (size_t)tok * CC + col);
                    float2 o2 = *op;
                    o2.x += gv * (c[rr*2+0] + bb.x);
                    o2.y += gv * (c[rr*2+1] + bb.y);
                    *op = o2;
                }
            }
        }
}

// ---------------- host launcher ----------------
extern "C" void kernel_launch(void* const* d_in, const int* in_sizes, int n_in,
                              void* d_out, int out_size) {
    const float* x     = (const float*)d_in[0];
    const float* noise = (const float*)d_in[1];
    const float* ln1_g = (const float*)d_in[2];
    const float* ln1_b = (const float*)d_in[3];
    const float* ln2_g = (const float*)d_in[4];
    const float* ln2_b = (const float*)d_in[5];
    const float* Wq    = (const float*)d_in[6];
    const float* Wk    = (const float*)d_in[7];
    const float* Wv    = (const float*)d_in[8];
    const float* Wp    = (const float*)d_in[9];
    const float* bp    = (const float*)d_in[10];
    const float* Wr    = (const float*)d_in[11];
    const float* br    = (const float*)d_in[12];
    const float* Wn    = (const float*)d_in[13];
    const float* bn    = (const float*)d_in[14];
    const float* W1    = (const float*)d_in[15];
    const float* b1    = (const float*)d_in[16];
    const float* W2    = (const float*)d_in[17];
    const float* b2    = (const float*)d_in[18];
    float* out = (float*)d_out;

    // LN1
    ln_kernel<<<TT, 256>>>(x, ln1_g, ln1_b, 0);
    // QKV (3xTF32)
    dim3 gq(TT / 128, HH);
    qkv_tc<<<gq, 256>>>(Wq, 0);
    qkv_tc<<<gq, 256>>>(Wk, 1);
    qkv_tc<<<gq, 256>>>(Wv, 2);
    // attention (tensor-core 3xTF32 flash)
    attn_tc<<<dim3(TT / 128, HH), 256>>>();
    // proj + residual -> out (3xTF32)
    proj_tc<<<dim3(CC / 64, TT / 128), 256>>>(Wp, bp, x, out);
    // LN2 on x1
    ln_kernel<<<TT, 256>>>(out, ln2_g, ln2_b, 1);
    // router + lists (fp32)
    router_kernel<<<TT, 256>>>(Wr, br, Wn, bn, noise);
    build_lists<<<1, 256>>>();
    // MoE experts (1xTF32), sequential
    for (int e = 0; e < EE; e++) {
        moe1_tc<<<dim3(FF / 64, TT / 128), 256>>>(W1, b1, e);
        moe2_tc<<<dim3(CC / 64, TT / 128), 256>>>(W2, b2, out, e);
    }
}

// round 15
// speedup vs baseline: 1.0555x; 1.0555x over previous
#include <cuda_runtime.h>
#include <cuda_bf16.h>
#include <math.h>

#define TT 2048
#define CC 1024
#define HH 16
#define DD 64
#define EE 8
#define FF 4096

// ---------------- scratch (static device globals; no allocation) ----------------
__device__ float g_xn [TT*CC];
__device__ float g_xn2[TT*CC];
__device__ float g_att[TT*CC];
__device__ float g_q[HH*TT*DD];
__device__ float g_k[HH*TT*DD];
__device__ float g_v[HH*TT*DD];
__device__ float g_gate[TT*EE];
__device__ int   g_list [EE*TT];
__device__ float g_lgate[EE*TT];
__device__ int   g_count[EE];
__device__ float g_h[TT*FF];

// ---------------- tf32 helpers ----------------
__device__ __forceinline__ unsigned f2tf(float f) {
    unsigned u;
    asm("cvt.rna.tf32.f32 %0, %1;" : "=r"(u) : "f"(f));
    return u;
}
__device__ __forceinline__ void cvt4(unsigned* dst, float4 v) {
    dst[0] = f2tf(v.x); dst[1] = f2tf(v.y); dst[2] = f2tf(v.z); dst[3] = f2tf(v.w);
}
__device__ __forceinline__ void split4(unsigned* hi, unsigned* lo, float4 v) {
    float f[4] = {v.x, v.y, v.z, v.w};
#pragma unroll
    for (int i = 0; i < 4; i++) {
        unsigned h = f2tf(f[i]);
        hi[i] = h;
        float hf = __uint_as_float(h);
        lo[i] = f2tf(f[i] - hf);
    }
}
__device__ __forceinline__ void mma_tf32(float* c, const unsigned* a, const unsigned* b) {
    asm volatile("mma.sync.aligned.m16n8k8.row.col.f32.tf32.tf32.f32 "
                 "{%0,%1,%2,%3},{%4,%5,%6,%7},{%8,%9},{%0,%1,%2,%3};"
                 : "+f"(c[0]), "+f"(c[1]), "+f"(c[2]), "+f"(c[3])
                 : "r"(a[0]), "r"(a[1]), "r"(a[2]), "r"(a[3]),
                   "r"(b[0]), "r"(b[1]));
}

// ---------------- bf16 helpers (attention) ----------------
__device__ __forceinline__ void mma_bf16(float* c, const unsigned* a, const unsigned* b) {
    asm volatile("mma.sync.aligned.m16n8k16.row.col.f32.bf16.bf16.f32 "
                 "{%0,%1,%2,%3},{%4,%5,%6,%7},{%8,%9},{%0,%1,%2,%3};"
                 : "+f"(c[0]), "+f"(c[1]), "+f"(c[2]), "+f"(c[3])
                 : "r"(a[0]), "r"(a[1]), "r"(a[2]), "r"(a[3]),
                   "r"(b[0]), "r"(b[1]));
}
// pack 2 floats into bf16x2 hi + bf16x2 residual-lo (low half = first element)
__device__ __forceinline__ void bfpack2(float a, float b, unsigned& h, unsigned& l) {
    __nv_bfloat16 ah = __float2bfloat16_rn(a), bh = __float2bfloat16_rn(b);
    float ar = a - __bfloat162float(ah);
    float br = b - __bfloat162float(bh);
    h = (unsigned)__bfloat16_as_ushort(ah) |
        ((unsigned)__bfloat16_as_ushort(bh) << 16);
    l = (unsigned)__bfloat16_as_ushort(__float2bfloat16_rn(ar)) |
        ((unsigned)__bfloat16_as_ushort(__float2bfloat16_rn(br)) << 16);
}

#define AP 36    // As row stride, 32-K-chunk tf32 kernels
#define BP 72    // Bs row stride
#define AP2 20   // As row stride, 16-K-chunk 3x kernels

// ---- 1x tf32 chunk (K=32) ----
#define MMA_CHUNK(As, Bs, acc, wm, wn, g, t4)                                   \
    _Pragma("unroll")                                                           \
    for (int ks = 0; ks < 4; ks++) {                                            \
        int kb = ks * 8;                                                        \
        unsigned afr[2][4], bfr[4][2];                                          \
        _Pragma("unroll")                                                       \
        for (int mi = 0; mi < 2; mi++) {                                        \
            int r0 = (wm)*32 + mi*16 + (g);                                     \
            afr[mi][0] = As[r0  ][kb + (t4)];                                   \
            afr[mi][1] = As[r0+8][kb + (t4)];                                   \
            afr[mi][2] = As[r0  ][kb + 4 + (t4)];                               \
            afr[mi][3] = As[r0+8][kb + 4 + (t4)];                               \
        }                                                                       \
        _Pragma("unroll")                                                       \
        for (int ni = 0; ni < 4; ni++) {                                        \
            int c0 = (wn)*32 + ni*8 + (g);                                      \
            bfr[ni][0] = Bs[kb + (t4)    ][c0];                                 \
            bfr[ni][1] = Bs[kb + 4 + (t4)][c0];                                 \
        }                                                                       \
        _Pragma("unroll")                                                       \
        for (int mi = 0; mi < 2; mi++)                                          \
            _Pragma("unroll")                                                   \
            for (int ni = 0; ni < 4; ni++)                                      \
                mma_tf32(acc[mi][ni], afr[mi], bfr[ni]);                        \
    }

// ---- 3x tf32 chunk (K=16, hi/lo split operands) ----
#define MMA_CHUNK3(Ah, Al, Bh, Bl, acc, wm, wn, g, t4)                          \
    _Pragma("unroll")                                                           \
    for (int ks = 0; ks < 2; ks++) {                                            \
        int kb = ks * 8;                                                        \
        unsigned ah[2][4], al[2][4], bh[4][2], bl[4][2];                        \
        _Pragma("unroll")                                                       \
        for (int mi = 0; mi < 2; mi++) {                                        \
            int r0 = (wm)*32 + mi*16 + (g);                                     \
            ah[mi][0]=Ah[r0  ][kb+(t4)];   al[mi][0]=Al[r0  ][kb+(t4)];         \
            ah[mi][1]=Ah[r0+8][kb+(t4)];   al[mi][1]=Al[r0+8][kb+(t4)];         \
            ah[mi][2]=Ah[r0  ][kb+4+(t4)]; al[mi][2]=Al[r0  ][kb+4+(t4)];       \
            ah[mi][3]=Ah[r0+8][kb+4+(t4)]; al[mi][3]=Al[r0+8][kb+4+(t4)];       \
        }                                                                       \
        _Pragma("unroll")                                                       \
        for (int ni = 0; ni < 4; ni++) {                                        \
            int c0 = (wn)*32 + ni*8 + (g);                                      \
            bh[ni][0]=Bh[kb+(t4)  ][c0];   bl[ni][0]=Bl[kb+(t4)  ][c0];         \
            bh[ni][1]=Bh[kb+4+(t4)][c0];   bl[ni][1]=Bl[kb+4+(t4)][c0];         \
        }                                                                       \
        _Pragma("unroll")                                                       \
        for (int mi = 0; mi < 2; mi++)                                          \
            _Pragma("unroll")                                                   \
            for (int ni = 0; ni < 4; ni++) {                                    \
                mma_tf32(acc[mi][ni], ah[mi], bh[ni]);                          \
                mma_tf32(acc[mi][ni], ah[mi], bl[ni]);                          \
                mma_tf32(acc[mi][ni], al[mi], bh[ni]);                          \
            }                                                                   \
    }

// ---------------- LayerNorm ----------------
__global__ void ln_kernel(const float* __restrict__ x, const float* __restrict__ gw,
                          const float* __restrict__ bw, int which) {
    int t = blockIdx.x;
    int tid = threadIdx.x;
    const float* row = x + (size_t)t * CC;
    float vals[4];
    float s = 0.f, s2 = 0.f;
#pragma unroll
    for (int i = 0; i < 4; i++) {
        float v = row[tid + i * 256];
        vals[i] = v; s += v; s2 += v * v;
    }
#pragma unroll
    for (int o = 16; o > 0; o >>= 1) {
        s  += __shfl_xor_sync(0xffffffffu, s, o);
        s2 += __shfl_xor_sync(0xffffffffu, s2, o);
    }
    __shared__ float red[2][8];
    __shared__ float smean, srstd;
    if ((tid & 31) == 0) { red[0][tid >> 5] = s; red[1][tid >> 5] = s2; }
    __syncthreads();
    if (tid < 32) {
        float a  = (tid < 8) ? red[0][tid] : 0.f;
        float a2 = (tid < 8) ? red[1][tid] : 0.f;
#pragma unroll
        for (int o = 4; o > 0; o >>= 1) {
            a  += __shfl_xor_sync(0xffffffffu, a, o);
            a2 += __shfl_xor_sync(0xffffffffu, a2, o);
        }
        if (tid == 0) {
            float m = a * (1.f / CC);
            smean = m;
            srstd = rsqrtf(a2 * (1.f / CC) - m * m + 1e-5f);
        }
    }
    __syncthreads();
    float m = smean, r = srstd;
    float* orow = (which == 0 ? g_xn : g_xn2) + (size_t)t * CC;
#pragma unroll
    for (int i = 0; i < 4; i++) {
        int c = tid + i * 256;
        orow[c] = (vals[i] - m) * r * gw[c] + bw[c];
    }
}

// ---------------- QKV 3xTF32 GEMM: tile 128x64, K-chunk 16, grid (Mtiles, H) ----------------
__global__ __launch_bounds__(256, 2) void qkv_tc(const float* __restrict__ W, int which) {
    int h = blockIdx.y;
    int m0 = blockIdx.x * 128;
    const float* B = W + (size_t)h * CC * DD;
    float* O = (which == 0 ? g_q : which == 1 ? g_k : g_v) + (size_t)h * TT * DD;
    __shared__ unsigned Ah[128][AP2], Al[128][AP2];
    __shared__ unsigned Bh[16][BP],  Bl[16][BP];
    int tid = threadIdx.x, lane = tid & 31, warp = tid >> 5;
    int wm = warp >> 1, wn = warp & 1, g = lane >> 2, t4 = lane & 3;
    float acc[2][4][4] = {};
    for (int k0 = 0; k0 < CC; k0 += 16) {
        float4 av[2], bv;
#pragma unroll
        for (int i = 0; i < 2; i++) {
            int idx = tid + i * 256, r = idx >> 2, c4 = (idx & 3) * 4;
            av[i] = *(const float4*)(g_xn + (size_t)(m0 + r) * CC + k0 + c4);
        }
        {
            int r = tid >> 4, c4 = (tid & 15) * 4;
            bv = *(const float4*)(B + (size_t)(k0 + r) * DD + c4);
        }
        __syncthreads();
#pragma unroll
        for (int i = 0; i < 2; i++) {
            int idx = tid + i * 256, r = idx >> 2, c4 = (idx & 3) * 4;
            split4(&Ah[r][c4], &Al[r][c4], av[i]);
        }
        {
            int r = tid >> 4, c4 = (tid & 15) * 4;
            split4(&Bh[r][c4], &Bl[r][c4], bv);
        }
        __syncthreads();
        MMA_CHUNK3(Ah, Al, Bh, Bl, acc, wm, wn, g, t4)
    }
#pragma unroll
    for (int mi = 0; mi < 2; mi++)
#pragma unroll
        for (int ni = 0; ni < 4; ni++) {
            int row = m0 + wm*32 + mi*16 + g;
            int col = wn*32 + ni*8 + 2*t4;
            float* c = acc[mi][ni];
            *(float2*)(O + (size_t)row * DD + col)     = make_float2(c[0], c[1]);
            *(float2*)(O + (size_t)(row+8) * DD + col) = make_float2(c[2], c[3]);
        }
}

// ---------------- Flash attention, bf16 tensor-core (3-term split) ----------------
// block: 128 Q rows x 1 head, 8 warps; warp = 16 rows x 64-key tile.
// Q in registers (split bf16 A-frags); K as [d2][key] packed d-pairs; V as [key2][d] packed key-pairs.
// P C-layout regs pack directly into bf16 A-frags (no shuffle transpose).
__global__ __launch_bounds__(256) void attn_bf() {
    int h  = blockIdx.y;
    int mi = (TT / 128 - 1) - blockIdx.x;     // heavy blocks first
    int m0 = mi * 128;
    const float* Q = g_q + (size_t)h * TT * DD;
    const float* K = g_k + (size_t)h * TT * DD;
    const float* V = g_v + (size_t)h * TT * DD;
    __shared__ unsigned Kth[32][68], Ktl[32][68];   // K^T packed: [d/2][key]
    __shared__ unsigned Vth[32][68], Vtl[32][68];   // V packed:   [key/2][d]
    int tid = threadIdx.x, lane = tid & 31, warp = tid >> 5;
    int g = lane >> 2, t4 = lane & 3;
    int wr = m0 + warp * 16;
    int qrow = wr + g;

    // Q A-fragments (4 k16 chunks over D=64), pre-scaled by C^-0.5, bf16 hi/lo
    unsigned qh[4][4], ql[4][4];
    const float sc = 0.03125f;
#pragma unroll
    for (int kc = 0; kc < 4; kc++) {
        float2 f0 = *(const float2*)(Q + (size_t)qrow * DD + kc * 16 + 2 * t4);
        float2 f1 = *(const float2*)(Q + (size_t)(qrow + 8) * DD + kc * 16 + 2 * t4);
        float2 f2 = *(const float2*)(Q + (size_t)qrow * DD + kc * 16 + 8 + 2 * t4);
        float2 f3 = *(const float2*)(Q + (size_t)(qrow + 8) * DD + kc * 16 + 8 + 2 * t4);
        bfpack2(f0.x * sc, f0.y * sc, qh[kc][0], ql[kc][0]);
        bfpack2(f1.x * sc, f1.y * sc, qh[kc][1], ql[kc][1]);
        bfpack2(f2.x * sc, f2.y * sc, qh[kc][2], ql[kc][2]);
        bfpack2(f3.x * sc, f3.y * sc, qh[kc][3], ql[kc][3]);
    }

    float o[8][4] = {};
    float mrow0 = -INFINITY, mrow1 = -INFINITY;
    float lrow0 = 0.f, lrow1 = 0.f;

    int ntiles = 2 * (mi + 1);                 // 64-key tiles
    for (int st = 0; st < ntiles; st++) {
        int s0 = st * 64;
        __syncthreads();
        // ---- stage K: [d2][key] packed d-pairs ----
#pragma unroll
        for (int i = 0; i < 4; i++) {
            int idx = tid + i * 256;
            int key = idx >> 4, d4 = idx & 15;
            float4 k4 = *(const float4*)(K + (size_t)(s0 + key) * DD + d4 * 4);
            unsigned h0, l0, h1, l1;
            bfpack2(k4.x, k4.y, h0, l0);
            bfpack2(k4.z, k4.w, h1, l1);
            Kth[d4 * 2][key] = h0; Kth[d4 * 2 + 1][key] = h1;
            Ktl[d4 * 2][key] = l0; Ktl[d4 * 2 + 1][key] = l1;
        }
        // ---- stage V: [key2][d] packed key-pairs ----
#pragma unroll
        for (int i = 0; i < 2; i++) {
            int idx = tid + i * 256;
            int k2 = idx >> 4, d4 = idx & 15;
            float4 va = *(const float4*)(V + (size_t)(s0 + 2 * k2) * DD + d4 * 4);
            float4 vb = *(const float4*)(V + (size_t)(s0 + 2 * k2 + 1) * DD + d4 * 4);
            float fa[4] = {va.x, va.y, va.z, va.w};
            float fb[4] = {vb.x, vb.y, vb.z, vb.w};
#pragma unroll
            for (int j = 0; j < 4; j++) {
                unsigned hv, lv;
                bfpack2(fa[j], fb[j], hv, lv);
                Vth[k2][d4 * 4 + j] = hv;
                Vtl[k2][d4 * 4 + j] = lv;
            }
        }
        __syncthreads();

        if (s0 > wr + 15) continue;            // fully masked for this warp

        // ---- S = Q @ K^T (bf16 3-term), 8 n8-tiles over 64 keys ----
        float sfr[8][4] = {};
#pragma unroll
        for (int kc = 0; kc < 4; kc++) {
#pragma unroll
            for (int ni = 0; ni < 8; ni++) {
                int col = ni * 8 + g;
                unsigned bh[2], bl[2];
                bh[0] = Kth[kc * 8 + t4][col]; bh[1] = Kth[kc * 8 + 4 + t4][col];
                bl[0] = Ktl[kc * 8 + t4][col]; bl[1] = Ktl[kc * 8 + 4 + t4][col];
                mma_bf16(sfr[ni], qh[kc], bh);
                mma_bf16(sfr[ni], qh[kc], bl);
                mma_bf16(sfr[ni], ql[kc], bh);
            }
        }

        // ---- causal mask ----
        if (s0 + 63 > wr) {
#pragma unroll
            for (int ni = 0; ni < 8; ni++) {
                int c = s0 + ni * 8 + 2 * t4;
                if (c     > qrow)     sfr[ni][0] = -INFINITY;
                if (c + 1 > qrow)     sfr[ni][1] = -INFINITY;
                if (c     > qrow + 8) sfr[ni][2] = -INFINITY;
                if (c + 1 > qrow + 8) sfr[ni][3] = -INFINITY;
            }
        }

        // ---- online softmax (rows qrow, qrow+8; quad reduction) ----
        float tmax0 = -INFINITY, tmax1 = -INFINITY;
#pragma unroll
        for (int ni = 0; ni < 8; ni++) {
            tmax0 = fmaxf(tmax0, fmaxf(sfr[ni][0], sfr[ni][1]));
            tmax1 = fmaxf(tmax1, fmaxf(sfr[ni][2], sfr[ni][3]));
        }
        tmax0 = fmaxf(tmax0, __shfl_xor_sync(0xffffffffu, tmax0, 1));
        tmax0 = fmaxf(tmax0, __shfl_xor_sync(0xffffffffu, tmax0, 2));
        tmax1 = fmaxf(tmax1, __shfl_xor_sync(0xffffffffu, tmax1, 1));
        tmax1 = fmaxf(tmax1, __shfl_xor_sync(0xffffffffu, tmax1, 2));
        float mn0 = fmaxf(mrow0, tmax0), mn1 = fmaxf(mrow1, tmax1);
        float cor0 = __expf(mrow0 - mn0), cor1 = __expf(mrow1 - mn1);
        mrow0 = mn0; mrow1 = mn1;
        float rs0 = 0.f, rs1 = 0.f;
#pragma unroll
        for (int ni = 0; ni < 8; ni++) {
            sfr[ni][0] = __expf(sfr[ni][0] - mn0);
            sfr[ni][1] = __expf(sfr[ni][1] - mn0);
            sfr[ni][2] = __expf(sfr[ni][2] - mn1);
            sfr[ni][3] = __expf(sfr[ni][3] - mn1);
            rs0 += sfr[ni][0] + sfr[ni][1];
            rs1 += sfr[ni][2] + sfr[ni][3];
        }
        rs0 += __shfl_xor_sync(0xffffffffu, rs0, 1);
        rs0 += __shfl_xor_sync(0xffffffffu, rs0, 2);
        rs1 += __shfl_xor_sync(0xffffffffu, rs1, 1);
        rs1 += __shfl_xor_sync(0xffffffffu, rs1, 2);
        lrow0 = lrow0 * cor0 + rs0;
        lrow1 = lrow1 * cor1 + rs1;
#pragma unroll
        for (int ni = 0; ni < 8; ni++) {
            o[ni][0] *= cor0; o[ni][1] *= cor0;
            o[ni][2] *= cor1; o[ni][3] *= cor1;
        }

        // ---- P packs directly into bf16 A-frags; O += P @ V (3-term) ----
#pragma unroll
        for (int j = 0; j < 4; j++) {          // key chunks of 16
            unsigned pah[4], pal[4];
            bfpack2(sfr[2*j][0],   sfr[2*j][1],   pah[0], pal[0]);
            bfpack2(sfr[2*j][2],   sfr[2*j][3],   pah[1], pal[1]);
            bfpack2(sfr[2*j+1][0], sfr[2*j+1][1], pah[2], pal[2]);
            bfpack2(sfr[2*j+1][2], sfr[2*j+1][3], pah[3], pal[3]);
#pragma unroll
            for (int ni = 0; ni < 8; ni++) {
                int col = ni * 8 + g;
                unsigned bh[2], bl[2];
                bh[0] = Vth[j * 8 + t4][col]; bh[1] = Vth[j * 8 + 4 + t4][col];
                bl[0] = Vtl[j * 8 + t4][col]; bl[1] = Vtl[j * 8 + 4 + t4][col];
                mma_bf16(o[ni], pah, bh);
                mma_bf16(o[ni], pah, bl);
                mma_bf16(o[ni], pal, bh);
            }
        }
    }

    float inv0 = 1.f / lrow0, inv1 = 1.f / lrow1;
#pragma unroll
    for (int ni = 0; ni < 8; ni++) {
        int col = h * DD + ni * 8 + 2 * t4;
        *(float2*)(g_att + (size_t)qrow * CC + col) =
            make_float2(o[ni][0] * inv0, o[ni][1] * inv0);
        *(float2*)(g_att + (size_t)(qrow + 8) * CC + col) =
            make_float2(o[ni][2] * inv1, o[ni][3] * inv1);
    }
}

// ---------------- proj 3xTF32 GEMM + bias + residual ----------------
__global__ __launch_bounds__(256, 2) void proj_tc(const float* __restrict__ W, const float* __restrict__ bias,
                         const float* __restrict__ xres, float* __restrict__ out) {
    int m0 = blockIdx.y * 128, n0 = blockIdx.x * 64;
    __shared__ unsigned Ah[128][AP2], Al[128][AP2];
    __shared__ unsigned Bh[16][BP],  Bl[16][BP];
    int tid = threadIdx.x, lane = tid & 31, warp = tid >> 5;
    int wm = warp >> 1, wn = warp & 1, g = lane >> 2, t4 = lane & 3;
    float acc[2][4][4] = {};
    for (int k0 = 0; k0 < CC; k0 += 16) {
        float4 av[2], bv;
#pragma unroll
        for (int i = 0; i < 2; i++) {
            int idx = tid + i * 256, r = idx >> 2, c4 = (idx & 3) * 4;
            av[i] = *(const float4*)(g_att + (size_t)(m0 + r) * CC + k0 + c4);
        }
        {
            int r = tid >> 4, c4 = (tid & 15) * 4;
            bv = *(const float4*)(W + (size_t)(k0 + r) * CC + n0 + c4);
        }
        __syncthreads();
#pragma unroll
        for (int i = 0; i < 2; i++) {
            int idx = tid + i * 256, r = idx >> 2, c4 = (idx & 3) * 4;
            split4(&Ah[r][c4], &Al[r][c4], av[i]);
        }
        {
            int r = tid >> 4, c4 = (tid & 15) * 4;
            split4(&Bh[r][c4], &Bl[r][c4], bv);
        }
        __syncthreads();
        MMA_CHUNK3(Ah, Al, Bh, Bl, acc, wm, wn, g, t4)
    }
#pragma unroll
    for (int mi = 0; mi < 2; mi++)
#pragma unroll
        for (int ni = 0; ni < 4; ni++) {
            int row = m0 + wm*32 + mi*16 + g;
            int col = n0 + wn*32 + ni*8 + 2*t4;
            float* c = acc[mi][ni];
            float2 bb = *(const float2*)(bias + col);
#pragma unroll
            for (int rr = 0; rr < 2; rr++) {
                size_t idx = (size_t)(row + rr*8) * CC + col;
                float2 xr = *(const float2*)(xres + idx);
                *(float2*)(out + idx) = make_float2(xr.x + c[rr*2+0] + bb.x,
                                                    xr.y + c[rr*2+1] + bb.y);
            }
        }
}

// ---------------- router: noisy top-2 gate (fp32) ----------------
__global__ void router_kernel(const float* __restrict__ Wr, const float* __restrict__ br,
                              const float* __restrict__ Wn, const float* __restrict__ bn,
                              const float* __restrict__ noise) {
    int t = blockIdx.x;
    int tid = threadIdx.x, e = tid >> 5, lane = tid & 31;
    const float* xr = g_xn2 + (size_t)t * CC;
    float sl = 0.f, sn = 0.f;
    for (int c = lane; c < CC; c += 32) {
        float xv = xr[c];
        sl += xv * Wr[c * EE + e];
        sn += xv * Wn[c * EE + e];
    }
#pragma unroll
    for (int o = 16; o > 0; o >>= 1) {
        sl += __shfl_xor_sync(0xffffffffu, sl, o);
        sn += __shfl_xor_sync(0xffffffffu, sn, o);
    }
    __shared__ float s_noisy[EE];
    if (lane == 0) {
        float lg = sl + br[e];
        float nl = sn + bn[e];
        float sp = (nl > 20.f) ? nl : log1pf(expf(nl));
        s_noisy[e] = lg + noise[(size_t)t * EE + e] * sp;
    }
    __syncthreads();
    if (tid == 0) {
        float n[EE];
#pragma unroll
        for (int i = 0; i < EE; i++) n[i] = s_noisy[i];
        int i1 = 0;
        for (int i = 1; i < EE; i++) if (n[i] > n[i1]) i1 = i;
        int i2 = -1;
        for (int i = 0; i < EE; i++) {
            if (i == i1) continue;
            if (i2 < 0 || n[i] > n[i2]) i2 = i;
        }
        float mx = fmaxf(n[i1], n[i2]);
        float e1 = __expf(n[i1] - mx), e2 = __expf(n[i2] - mx);
        float inv = 1.f / (e1 + e2);
#pragma unroll
        for (int i = 0; i < EE; i++) g_gate[(size_t)t * EE + i] = 0.f;
        g_gate[(size_t)t * EE + i1] = e1 * inv;
        g_gate[(size_t)t * EE + i2] = e2 * inv;
    }
}

// ---------------- deterministic per-expert token lists ----------------
__global__ void build_lists() {
    int e = threadIdx.x >> 5, lane = threadIdx.x & 31;
    int cnt = 0;
    for (int base = 0; base < TT; base += 32) {
        int t = base + lane;
        float gv = g_gate[(size_t)t * EE + e];
        unsigned mask = __ballot_sync(0xffffffffu, gv > 0.f);
        if (gv > 0.f) {
            int pos = cnt + __popc(mask & ((1u << lane) - 1u));
            g_list [e * TT + pos] = t;
            g_lgate[e * TT + pos] = gv;
        }
        cnt += __popc(mask);
    }
    if (lane == 0) g_count[e] = cnt;
}

// ---------------- MoE layer 1 (1xTF32, gathered A): h = relu(xn2[list]@W1[e] + b1) ----------------
__global__ __launch_bounds__(256, 2) void moe1_tc(const float* __restrict__ W1, const float* __restrict__ b1, int e) {
    int Ne = g_count[e];
    int m0 = blockIdx.y * 128;
    if (m0 >= Ne) return;
    int n0 = blockIdx.x * 64;
    const float* B = W1 + (size_t)e * CC * FF;
    const float* bias = b1 + (size_t)e * FF;
    __shared__ unsigned As[128][AP];
    __shared__ unsigned Bs[32][BP];
    __shared__ int rows[128];
    int tid = threadIdx.x, lane = tid & 31, warp = tid >> 5;
    int wm = warp >> 1, wn = warp & 1, g = lane >> 2, t4 = lane & 3;
    if (tid < 128) rows[tid] = (m0 + tid < Ne) ? g_list[e * TT + m0 + tid] : 0;
    __syncthreads();
    float acc[2][4][4] = {};
    for (int k0 = 0; k0 < CC; k0 += 32) {
        float4 av[4], bv[2];
#pragma unroll
        for (int i = 0; i < 4; i++) {
            int idx = tid + i * 256, r = idx >> 3, c4 = (idx & 7) * 4;
            av[i] = *(const float4*)(g_xn2 + (size_t)rows[r] * CC + k0 + c4);
        }
#pragma unroll
        for (int i = 0; i < 2; i++) {
            int idx = tid + i * 256, r = idx >> 4, c4 = (idx & 15) * 4;
            bv[i] = *(const float4*)(B + (size_t)(k0 + r) * FF + n0 + c4);
        }
        __syncthreads();
#pragma unroll
        for (int i = 0; i < 4; i++) {
            int idx = tid + i * 256, r = idx >> 3, c4 = (idx & 7) * 4;
            cvt4(&As[r][c4], av[i]);
        }
#pragma unroll
        for (int i = 0; i < 2; i++) {
            int idx = tid + i * 256, r = idx >> 4, c4 = (idx & 15) * 4;
            cvt4(&Bs[r][c4], bv[i]);
        }
        __syncthreads();
        MMA_CHUNK(As, Bs, acc, wm, wn, g, t4)
    }
#pragma unroll
    for (int mi = 0; mi < 2; mi++)
#pragma unroll
        for (int ni = 0; ni < 4; ni++) {
            int row = m0 + wm*32 + mi*16 + g;
            int col = n0 + wn*32 + ni*8 + 2*t4;
            float* c = acc[mi][ni];
            float2 bb = *(const float2*)(bias + col);
#pragma unroll
            for (int rr = 0; rr < 2; rr++) {
                int m = row + rr*8;
                if (m < Ne)
                    *(float2*)(g_h + (size_t)m * FF + col) =
                        make_float2(fmaxf(c[rr*2+0] + bb.x, 0.f),
                                    fmaxf(c[rr*2+1] + bb.y, 0.f));
            }
        }
}

// ---------------- MoE layer 2 (1xTF32): out[tok] += gate * (h@W2[e] + b2) ----------------
__global__ __launch_bounds__(256, 2) void moe2_tc(const float* __restrict__ W2, const float* __restrict__ b2,
                         float* __restrict__ out, int e) {
    int Ne = g_count[e];
    int m0 = blockIdx.y * 128;
    if (m0 >= Ne) return;
    int n0 = blockIdx.x * 64;
    const float* B = W2 + (size_t)e * FF * CC;
    const float* bias = b2 + (size_t)e * CC;
    __shared__ unsigned As[128][AP];
    __shared__ unsigned Bs[32][BP];
    int tid = threadIdx.x, lane = tid & 31, warp = tid >> 5;
    int wm = warp >> 1, wn = warp & 1, g = lane >> 2, t4 = lane & 3;
    float acc[2][4][4] = {};
    for (int k0 = 0; k0 < FF; k0 += 32) {
        float4 av[4], bv[2];
#pragma unroll
        for (int i = 0; i < 4; i++) {
            int idx = tid + i * 256, r = idx >> 3, c4 = (idx & 7) * 4;
            av[i] = *(const float4*)(g_h + (size_t)(m0 + r) * FF + k0 + c4);
        }
#pragma unroll
        for (int i = 0; i < 2; i++) {
            int idx = tid + i * 256, r = idx >> 4, c4 = (idx & 15) * 4;
            bv[i] = *(const float4*)(B + (size_t)(k0 + r) * CC + n0 + c4);
        }
        __syncthreads();
#pragma unroll
        for (int i = 0; i < 4; i++) {
            int idx = tid + i * 256, r = idx >> 3, c4 = (idx & 7) * 4;
            cvt4(&As[r][c4], av[i]);
        }
#pragma unroll
        for (int i = 0; i < 2; i++) {
            int idx = tid + i * 256, r = idx >> 4, c4 = (idx & 15) * 4;
            cvt4(&Bs[r][c4], bv[i]);
        }
        __syncthreads();
        MMA_CHUNK(As, Bs, acc, wm, wn, g, t4)
    }
#pragma unroll
    for (int mi = 0; mi < 2; mi++)
#pragma unroll
        for (int ni = 0; ni < 4; ni++) {
            int row = m0 + wm*32 + mi*16 + g;
            int col = n0 + wn*32 + ni*8 + 2*t4;
            float* c = acc[mi][ni];
            float2 bb = *(const float2*)(bias + col);
#pragma unroll
            for (int rr = 0; rr < 2; rr++) {
                int m = row + rr*8;
                if (m < Ne) {
                    int tok = g_list[e * TT + m];
                    float gv = g_lgate[e * TT + m];
                    float2* op = (float2*)(out + (size_t)tok * CC + col);
                    float2 o2 = *op;
                    o2.x += gv * (c[rr*2+0] + bb.x);
                    o2.y += gv * (c[rr*2+1] + bb.y);
                    *op = o2;
                }
            }
        }
}

// ---------------- host launcher ----------------
extern "C" void kernel_launch(void* const* d_in, const int* in_sizes, int n_in,
                              void* d_out, int out_size) {
    const float* x     = (const float*)d_in[0];
    const float* noise = (const float*)d_in[1];
    const float* ln1_g = (const float*)d_in[2];
    const float* ln1_b = (const float*)d_in[3];
    const float* ln2_g = (const float*)d_in[4];
    const float* ln2_b = (const float*)d_in[5];
    const float* Wq    = (const float*)d_in[6];
    const float* Wk    = (const float*)d_in[7];
    const float* Wv    = (const float*)d_in[8];
    const float* Wp    = (const float*)d_in[9];
    const float* bp    = (const float*)d_in[10];
    const float* Wr    = (const float*)d_in[11];
    const float* br    = (const float*)d_in[12];
    const float* Wn    = (const float*)d_in[13];
    const float* bn    = (const float*)d_in[14];
    const float* W1    = (const float*)d_in[15];
    const float* b1    = (const float*)d_in[16];
    const float* W2    = (const float*)d_in[17];
    const float* b2    = (const float*)d_in[18];
    float* out = (float*)d_out;

    // LN1
    ln_kernel<<<TT, 256>>>(x, ln1_g, ln1_b, 0);
    // QKV (3xTF32 — router-sensitive path stays high precision)
    dim3 gq(TT / 128, HH);
    qkv_tc<<<gq, 256>>>(Wq, 0);
    qkv_tc<<<gq, 256>>>(Wk, 1);
    qkv_tc<<<gq, 256>>>(Wv, 2);
    // attention (bf16 tensor-core flash, 3-term split)
    attn_bf<<<dim3(TT / 128, HH), 256>>>();
    // proj + residual -> out (3xTF32)
    proj_tc<<<dim3(CC / 64, TT / 128), 256>>>(Wp, bp, x, out);
    // LN2 on x1
    ln_kernel<<<TT, 256>>>(out, ln2_g, ln2_b, 1);
    // router + lists (fp32)
    router_kernel<<<TT, 256>>>(Wr, br, Wn, bn, noise);
    build_lists<<<1, 256>>>();
    // MoE experts (1xTF32), sequential
    for (int e = 0; e < EE; e++) {
        moe1_tc<<<dim3(FF / 64, TT / 128), 256>>>(W1, b1, e);
        moe2_tc<<<dim3(CC / 64, TT / 128), 256>>>(W2, b2, out, e);
    }
}

// round 17
// speedup vs baseline: 1.8426x; 1.7457x over previous
#include <cuda_runtime.h>
#include <cuda_bf16.h>
#include <math.h>

#define TT 2048
#define CC 1024
#define HH 16
#define DD 64
#define EE 8
#define FF 4096
#define NCOMP (2*TT)   // total compact rows across experts (top-2 => 4096)

// ---------------- scratch (static device globals; no allocation) ----------------
__device__ float g_xn [TT*CC];
__device__ float g_xn2[TT*CC];
__device__ float g_att[TT*CC];
__device__ float g_q[HH*TT*DD];
__device__ float g_k[HH*TT*DD];
__device__ float g_v[HH*TT*DD];
__device__ float g_gate[TT*EE];
__device__ int   g_count[EE];
__device__ int   g_off[EE];
__device__ int   g_ctok [NCOMP];
__device__ float g_cgate[NCOMP];
__device__ int   g_slot[TT*2];
__device__ float g_h[(size_t)NCOMP*FF];   // hidden per compact row
__device__ float g_y[(size_t)NCOMP*CC];   // gated expert output per compact row

// ---------------- tf32 helpers ----------------
__device__ __forceinline__ unsigned f2tf(float f) {
    unsigned u;
    asm("cvt.rna.tf32.f32 %0, %1;" : "=r"(u) : "f"(f));
    return u;
}
__device__ __forceinline__ void cvt4(unsigned* dst, float4 v) {
    dst[0] = f2tf(v.x); dst[1] = f2tf(v.y); dst[2] = f2tf(v.z); dst[3] = f2tf(v.w);
}
__device__ __forceinline__ void split4(unsigned* hi, unsigned* lo, float4 v) {
    float f[4] = {v.x, v.y, v.z, v.w};
#pragma unroll
    for (int i = 0; i < 4; i++) {
        unsigned h = f2tf(f[i]);
        hi[i] = h;
        float hf = __uint_as_float(h);
        lo[i] = f2tf(f[i] - hf);
    }
}
__device__ __forceinline__ void mma_tf32(float* c, const unsigned* a, const unsigned* b) {
    asm volatile("mma.sync.aligned.m16n8k8.row.col.f32.tf32.tf32.f32 "
                 "{%0,%1,%2,%3},{%4,%5,%6,%7},{%8,%9},{%0,%1,%2,%3};"
                 : "+f"(c[0]), "+f"(c[1]), "+f"(c[2]), "+f"(c[3])
                 : "r"(a[0]), "r"(a[1]), "r"(a[2]), "r"(a[3]),
                   "r"(b[0]), "r"(b[1]));
}

// ---------------- bf16 helpers (attention) ----------------
__device__ __forceinline__ void mma_bf16(float* c, const unsigned* a, const unsigned* b) {
    asm volatile("mma.sync.aligned.m16n8k16.row.col.f32.bf16.bf16.f32 "
                 "{%0,%1,%2,%3},{%4,%5,%6,%7},{%8,%9},{%0,%1,%2,%3};"
                 : "+f"(c[0]), "+f"(c[1]), "+f"(c[2]), "+f"(c[3])
                 : "r"(a[0]), "r"(a[1]), "r"(a[2]), "r"(a[3]),
                   "r"(b[0]), "r"(b[1]));
}
__device__ __forceinline__ void bfpack2(float a, float b, unsigned& h, unsigned& l) {
    __nv_bfloat16 ah = __float2bfloat16_rn(a), bh = __float2bfloat16_rn(b);
    float ar = a - __bfloat162float(ah);
    float br = b - __bfloat162float(bh);
    h = (unsigned)__bfloat16_as_ushort(ah) |
        ((unsigned)__bfloat16_as_ushort(bh) << 16);
    l = (unsigned)__bfloat16_as_ushort(__float2bfloat16_rn(ar)) |
        ((unsigned)__bfloat16_as_ushort(__float2bfloat16_rn(br)) << 16);
}

#define AP 36
#define BP 72
#define AP2 20

// ---- 1x tf32 chunk (K=32) ----
#define MMA_CHUNK(As, Bs, acc, wm, wn, g, t4)                                   \
    _Pragma("unroll")                                                           \
    for (int ks = 0; ks < 4; ks++) {                                            \
        int kb = ks * 8;                                                        \
        unsigned afr[2][4], bfr[4][2];                                          \
        _Pragma("unroll")                                                       \
        for (int mi = 0; mi < 2; mi++) {                                        \
            int r0 = (wm)*32 + mi*16 + (g);                                     \
            afr[mi][0] = As[r0  ][kb + (t4)];                                   \
            afr[mi][1] = As[r0+8][kb + (t4)];                                   \
            afr[mi][2] = As[r0  ][kb + 4 + (t4)];                               \
            afr[mi][3] = As[r0+8][kb + 4 + (t4)];                               \
        }                                                                       \
        _Pragma("unroll")                                                       \
        for (int ni = 0; ni < 4; ni++) {                                        \
            int c0 = (wn)*32 + ni*8 + (g);                                      \
            bfr[ni][0] = Bs[kb + (t4)    ][c0];                                 \
            bfr[ni][1] = Bs[kb + 4 + (t4)][c0];                                 \
        }                                                                       \
        _Pragma("unroll")                                                       \
        for (int mi = 0; mi < 2; mi++)                                          \
            _Pragma("unroll")                                                   \
            for (int ni = 0; ni < 4; ni++)                                      \
                mma_tf32(acc[mi][ni], afr[mi], bfr[ni]);                        \
    }

// ---- 3x tf32 chunk (K=16, hi/lo split operands) ----
#define MMA_CHUNK3(Ah, Al, Bh, Bl, acc, wm, wn, g, t4)                          \
    _Pragma("unroll")                                                           \
    for (int ks = 0; ks < 2; ks++) {                                            \
        int kb = ks * 8;                                                        \
        unsigned ah[2][4], al[2][4], bh[4][2], bl[4][2];                        \
        _Pragma("unroll")                                                       \
        for (int mi = 0; mi < 2; mi++) {                                        \
            int r0 = (wm)*32 + mi*16 + (g);                                     \
            ah[mi][0]=Ah[r0  ][kb+(t4)];   al[mi][0]=Al[r0  ][kb+(t4)];         \
            ah[mi][1]=Ah[r0+8][kb+(t4)];   al[mi][1]=Al[r0+8][kb+(t4)];         \
            ah[mi][2]=Ah[r0  ][kb+4+(t4)]; al[mi][2]=Al[r0  ][kb+4+(t4)];       \
            ah[mi][3]=Ah[r0+8][kb+4+(t4)]; al[mi][3]=Al[r0+8][kb+4+(t4)];       \
        }                                                                       \
        _Pragma("unroll")                                                       \
        for (int ni = 0; ni < 4; ni++) {                                        \
            int c0 = (wn)*32 + ni*8 + (g);                                      \
            bh[ni][0]=Bh[kb+(t4)  ][c0];   bl[ni][0]=Bl[kb+(t4)  ][c0];         \
            bh[ni][1]=Bh[kb+4+(t4)][c0];   bl[ni][1]=Bl[kb+4+(t4)][c0];         \
        }                                                                       \
        _Pragma("unroll")                                                       \
        for (int mi = 0; mi < 2; mi++)                                          \
            _Pragma("unroll")                                                   \
            for (int ni = 0; ni < 4; ni++) {                                    \
                mma_tf32(acc[mi][ni], ah[mi], bh[ni]);                          \
                mma_tf32(acc[mi][ni], ah[mi], bl[ni]);                          \
                mma_tf32(acc[mi][ni], al[mi], bh[ni]);                          \
            }                                                                   \
    }

// ---------------- LayerNorm ----------------
__global__ void ln_kernel(const float* __restrict__ x, const float* __restrict__ gw,
                          const float* __restrict__ bw, int which) {
    int t = blockIdx.x;
    int tid = threadIdx.x;
    const float* row = x + (size_t)t * CC;
    float vals[4];
    float s = 0.f, s2 = 0.f;
#pragma unroll
    for (int i = 0; i < 4; i++) {
        float v = row[tid + i * 256];
        vals[i] = v; s += v; s2 += v * v;
    }
#pragma unroll
    for (int o = 16; o > 0; o >>= 1) {
        s  += __shfl_xor_sync(0xffffffffu, s, o);
        s2 += __shfl_xor_sync(0xffffffffu, s2, o);
    }
    __shared__ float red[2][8];
    __shared__ float smean, srstd;
    if ((tid & 31) == 0) { red[0][tid >> 5] = s; red[1][tid >> 5] = s2; }
    __syncthreads();
    if (tid < 32) {
        float a  = (tid < 8) ? red[0][tid] : 0.f;
        float a2 = (tid < 8) ? red[1][tid] : 0.f;
#pragma unroll
        for (int o = 4; o > 0; o >>= 1) {
            a  += __shfl_xor_sync(0xffffffffu, a, o);
            a2 += __shfl_xor_sync(0xffffffffu, a2, o);
        }
        if (tid == 0) {
            float m = a * (1.f / CC);
            smean = m;
            srstd = rsqrtf(a2 * (1.f / CC) - m * m + 1e-5f);
        }
    }
    __syncthreads();
    float m = smean, r = srstd;
    float* orow = (which == 0 ? g_xn : g_xn2) + (size_t)t * CC;
#pragma unroll
    for (int i = 0; i < 4; i++) {
        int c = tid + i * 256;
        orow[c] = (vals[i] - m) * r * gw[c] + bw[c];
    }
}

// ---------------- QKV 3xTF32 GEMM, all three in one launch: grid (Mtiles, 3*H) ----------------
__global__ __launch_bounds__(256, 2) void qkv_all(const float* __restrict__ Wq,
                                                  const float* __restrict__ Wk,
                                                  const float* __restrict__ Wv) {
    int which = blockIdx.y / HH;
    int h = blockIdx.y % HH;
    int m0 = blockIdx.x * 128;
    const float* W = (which == 0 ? Wq : which == 1 ? Wk : Wv);
    const float* B = W + (size_t)h * CC * DD;
    float* O = (which == 0 ? g_q : which == 1 ? g_k : g_v) + (size_t)h * TT * DD;
    __shared__ unsigned Ah[128][AP2], Al[128][AP2];
    __shared__ unsigned Bh[16][BP],  Bl[16][BP];
    int tid = threadIdx.x, lane = tid & 31, warp = tid >> 5;
    int wm = warp >> 1, wn = warp & 1, g = lane >> 2, t4 = lane & 3;
    float acc[2][4][4] = {};
    for (int k0 = 0; k0 < CC; k0 += 16) {
        float4 av[2], bv;
#pragma unroll
        for (int i = 0; i < 2; i++) {
            int idx = tid + i * 256, r = idx >> 2, c4 = (idx & 3) * 4;
            av[i] = *(const float4*)(g_xn + (size_t)(m0 + r) * CC + k0 + c4);
        }
        {
            int r = tid >> 4, c4 = (tid & 15) * 4;
            bv = *(const float4*)(B + (size_t)(k0 + r) * DD + c4);
        }
        __syncthreads();
#pragma unroll
        for (int i = 0; i < 2; i++) {
            int idx = tid + i * 256, r = idx >> 2, c4 = (idx & 3) * 4;
            split4(&Ah[r][c4], &Al[r][c4], av[i]);
        }
        {
            int r = tid >> 4, c4 = (tid & 15) * 4;
            split4(&Bh[r][c4], &Bl[r][c4], bv);
        }
        __syncthreads();
        MMA_CHUNK3(Ah, Al, Bh, Bl, acc, wm, wn, g, t4)
    }
#pragma unroll
    for (int mi = 0; mi < 2; mi++)
#pragma unroll
        for (int ni = 0; ni < 4; ni++) {
            int row = m0 + wm*32 + mi*16 + g;
            int col = wn*32 + ni*8 + 2*t4;
            float* c = acc[mi][ni];
            *(float2*)(O + (size_t)row * DD + col)     = make_float2(c[0], c[1]);
            *(float2*)(O + (size_t)(row+8) * DD + col) = make_float2(c[2], c[3]);
        }
}

// ---------------- Flash attention, bf16 tensor-core (3-term split) ----------------
__global__ __launch_bounds__(256) void attn_bf() {
    int h  = blockIdx.y;
    int mi = (TT / 128 - 1) - blockIdx.x;
    int m0 = mi * 128;
    const float* Q = g_q + (size_t)h * TT * DD;
    const float* K = g_k + (size_t)h * TT * DD;
    const float* V = g_v + (size_t)h * TT * DD;
    __shared__ unsigned Kth[32][68], Ktl[32][68];
    __shared__ unsigned Vth[32][68], Vtl[32][68];
    int tid = threadIdx.x, lane = tid & 31, warp = tid >> 5;
    int g = lane >> 2, t4 = lane & 3;
    int wr = m0 + warp * 16;
    int qrow = wr + g;

    unsigned qh[4][4], ql[4][4];
    const float sc = 0.03125f;
#pragma unroll
    for (int kc = 0; kc < 4; kc++) {
        float2 f0 = *(const float2*)(Q + (size_t)qrow * DD + kc * 16 + 2 * t4);
        float2 f1 = *(const float2*)(Q + (size_t)(qrow + 8) * DD + kc * 16 + 2 * t4);
        float2 f2 = *(const float2*)(Q + (size_t)qrow * DD + kc * 16 + 8 + 2 * t4);
        float2 f3 = *(const float2*)(Q + (size_t)(qrow + 8) * DD + kc * 16 + 8 + 2 * t4);
        bfpack2(f0.x * sc, f0.y * sc, qh[kc][0], ql[kc][0]);
        bfpack2(f1.x * sc, f1.y * sc, qh[kc][1], ql[kc][1]);
        bfpack2(f2.x * sc, f2.y * sc, qh[kc][2], ql[kc][2]);
        bfpack2(f3.x * sc, f3.y * sc, qh[kc][3], ql[kc][3]);
    }

    float o[8][4] = {};
    float mrow0 = -INFINITY, mrow1 = -INFINITY;
    float lrow0 = 0.f, lrow1 = 0.f;

    int ntiles = 2 * (mi + 1);
    for (int st = 0; st < ntiles; st++) {
        int s0 = st * 64;
        __syncthreads();
#pragma unroll
        for (int i = 0; i < 4; i++) {
            int idx = tid + i * 256;
            int key = idx >> 4, d4 = idx & 15;
            float4 k4 = *(const float4*)(K + (size_t)(s0 + key) * DD + d4 * 4);
            unsigned h0, l0, h1, l1;
            bfpack2(k4.x, k4.y, h0, l0);
            bfpack2(k4.z, k4.w, h1, l1);
            Kth[d4 * 2][key] = h0; Kth[d4 * 2 + 1][key] = h1;
            Ktl[d4 * 2][key] = l0; Ktl[d4 * 2 + 1][key] = l1;
        }
#pragma unroll
        for (int i = 0; i < 2; i++) {
            int idx = tid + i * 256;
            int k2 = idx >> 4, d4 = idx & 15;
            float4 va = *(const float4*)(V + (size_t)(s0 + 2 * k2) * DD + d4 * 4);
            float4 vb = *(const float4*)(V + (size_t)(s0 + 2 * k2 + 1) * DD + d4 * 4);
            float fa[4] = {va.x, va.y, va.z, va.w};
            float fb[4] = {vb.x, vb.y, vb.z, vb.w};
#pragma unroll
            for (int j = 0; j < 4; j++) {
                unsigned hv, lv;
                bfpack2(fa[j], fb[j], hv, lv);
                Vth[k2][d4 * 4 + j] = hv;
                Vtl[k2][d4 * 4 + j] = lv;
            }
        }
        __syncthreads();

        if (s0 > wr + 15) continue;

        float sfr[8][4] = {};
#pragma unroll
        for (int kc = 0; kc < 4; kc++) {
#pragma unroll
            for (int ni = 0; ni < 8; ni++) {
                int col = ni * 8 + g;
                unsigned bh[2], bl[2];
                bh[0] = Kth[kc * 8 + t4][col]; bh[1] = Kth[kc * 8 + 4 + t4][col];
                bl[0] = Ktl[kc * 8 + t4][col]; bl[1] = Ktl[kc * 8 + 4 + t4][col];
                mma_bf16(sfr[ni], qh[kc], bh);
                mma_bf16(sfr[ni], qh[kc], bl);
                mma_bf16(sfr[ni], ql[kc], bh);
            }
        }

        if (s0 + 63 > wr) {
#pragma unroll
            for (int ni = 0; ni < 8; ni++) {
                int c = s0 + ni * 8 + 2 * t4;
                if (c     > qrow)     sfr[ni][0] = -INFINITY;
                if (c + 1 > qrow)     sfr[ni][1] = -INFINITY;
                if (c     > qrow + 8) sfr[ni][2] = -INFINITY;
                if (c + 1 > qrow + 8) sfr[ni][3] = -INFINITY;
            }
        }

        float tmax0 = -INFINITY, tmax1 = -INFINITY;
#pragma unroll
        for (int ni = 0; ni < 8; ni++) {
            tmax0 = fmaxf(tmax0, fmaxf(sfr[ni][0], sfr[ni][1]));
            tmax1 = fmaxf(tmax1, fmaxf(sfr[ni][2], sfr[ni][3]));
        }
        tmax0 = fmaxf(tmax0, __shfl_xor_sync(0xffffffffu, tmax0, 1));
        tmax0 = fmaxf(tmax0, __shfl_xor_sync(0xffffffffu, tmax0, 2));
        tmax1 = fmaxf(tmax1, __shfl_xor_sync(0xffffffffu, tmax1, 1));
        tmax1 = fmaxf(tmax1, __shfl_xor_sync(0xffffffffu, tmax1, 2));
        float mn0 = fmaxf(mrow0, tmax0), mn1 = fmaxf(mrow1, tmax1);
        float cor0 = __expf(mrow0 - mn0), cor1 = __expf(mrow1 - mn1);
        mrow0 = mn0; mrow1 = mn1;
        float rs0 = 0.f, rs1 = 0.f;
#pragma unroll
        for (int ni = 0; ni < 8; ni++) {
            sfr[ni][0] = __expf(sfr[ni][0] - mn0);
            sfr[ni][1] = __expf(sfr[ni][1] - mn0);
            sfr[ni][2] = __expf(sfr[ni][2] - mn1);
            sfr[ni][3] = __expf(sfr[ni][3] - mn1);
            rs0 += sfr[ni][0] + sfr[ni][1];
            rs1 += sfr[ni][2] + sfr[ni][3];
        }
        rs0 += __shfl_xor_sync(0xffffffffu, rs0, 1);
        rs0 += __shfl_xor_sync(0xffffffffu, rs0, 2);
        rs1 += __shfl_xor_sync(0xffffffffu, rs1, 1);
        rs1 += __shfl_xor_sync(0xffffffffu, rs1, 2);
        lrow0 = lrow0 * cor0 + rs0;
        lrow1 = lrow1 * cor1 + rs1;
#pragma unroll
        for (int ni = 0; ni < 8; ni++) {
            o[ni][0] *= cor0; o[ni][1] *= cor0;
            o[ni][2] *= cor1; o[ni][3] *= cor1;
        }

#pragma unroll
        for (int j = 0; j < 4; j++) {
            unsigned pah[4], pal[4];
            bfpack2(sfr[2*j][0],   sfr[2*j][1],   pah[0], pal[0]);
            bfpack2(sfr[2*j][2],   sfr[2*j][3],   pah[1], pal[1]);
            bfpack2(sfr[2*j+1][0], sfr[2*j+1][1], pah[2], pal[2]);
            bfpack2(sfr[2*j+1][2], sfr[2*j+1][3], pah[3], pal[3]);
#pragma unroll
            for (int ni = 0; ni < 8; ni++) {
                int col = ni * 8 + g;
                unsigned bh[2], bl[2];
                bh[0] = Vth[j * 8 + t4][col]; bh[1] = Vth[j * 8 + 4 + t4][col];
                bl[0] = Vtl[j * 8 + t4][col]; bl[1] = Vtl[j * 8 + 4 + t4][col];
                mma_bf16(o[ni], pah, bh);
                mma_bf16(o[ni], pah, bl);
                mma_bf16(o[ni], pal, bh);
            }
        }
    }

    float inv0 = 1.f / lrow0, inv1 = 1.f / lrow1;
#pragma unroll
    for (int ni = 0; ni < 8; ni++) {
        int col = h * DD + ni * 8 + 2 * t4;
        *(float2*)(g_att + (size_t)qrow * CC + col) =
            make_float2(o[ni][0] * inv0, o[ni][1] * inv0);
        *(float2*)(g_att + (size_t)(qrow + 8) * CC + col) =
            make_float2(o[ni][2] * inv1, o[ni][3] * inv1);
    }
}

// ---------------- proj 3xTF32 GEMM + bias + residual ----------------
__global__ __launch_bounds__(256, 2) void proj_tc(const float* __restrict__ W, const float* __restrict__ bias,
                         const float* __restrict__ xres, float* __restrict__ out) {
    int m0 = blockIdx.y * 128, n0 = blockIdx.x * 64;
    __shared__ unsigned Ah[128][AP2], Al[128][AP2];
    __shared__ unsigned Bh[16][BP],  Bl[16][BP];
    int tid = threadIdx.x, lane = tid & 31, warp = tid >> 5;
    int wm = warp >> 1, wn = warp & 1, g = lane >> 2, t4 = lane & 3;
    float acc[2][4][4] = {};
    for (int k0 = 0; k0 < CC; k0 += 16) {
        float4 av[2], bv;
#pragma unroll
        for (int i = 0; i < 2; i++) {
            int idx = tid + i * 256, r = idx >> 2, c4 = (idx & 3) * 4;
            av[i] = *(const float4*)(g_att + (size_t)(m0 + r) * CC + k0 + c4);
        }
        {
            int r = tid >> 4, c4 = (tid & 15) * 4;
            bv = *(const float4*)(W + (size_t)(k0 + r) * CC + n0 + c4);
        }
        __syncthreads();
#pragma unroll
        for (int i = 0; i < 2; i++) {
            int idx = tid + i * 256, r = idx >> 2, c4 = (idx & 3) * 4;
            split4(&Ah[r][c4], &Al[r][c4], av[i]);
        }
        {
            int r = tid >> 4, c4 = (tid & 15) * 4;
            split4(&Bh[r][c4], &Bl[r][c4], bv);
        }
        __syncthreads();
        MMA_CHUNK3(Ah, Al, Bh, Bl, acc, wm, wn, g, t4)
    }
#pragma unroll
    for (int mi = 0; mi < 2; mi++)
#pragma unroll
        for (int ni = 0; ni < 4; ni++) {
            int row = m0 + wm*32 + mi*16 + g;
            int col = n0 + wn*32 + ni*8 + 2*t4;
            float* c = acc[mi][ni];
            float2 bb = *(const float2*)(bias + col);
#pragma unroll
            for (int rr = 0; rr < 2; rr++) {
                size_t idx = (size_t)(row + rr*8) * CC + col;
                float2 xr = *(const float2*)(xres + idx);
                *(float2*)(out + idx) = make_float2(xr.x + c[rr*2+0] + bb.x,
                                                    xr.y + c[rr*2+1] + bb.y);
            }
        }
}

// ---------------- router: noisy top-2 gate (fp32) ----------------
__global__ void router_kernel(const float* __restrict__ Wr, const float* __restrict__ br,
                              const float* __restrict__ Wn, const float* __restrict__ bn,
                              const float* __restrict__ noise) {
    int t = blockIdx.x;
    int tid = threadIdx.x, e = tid >> 5, lane = tid & 31;
    const float* xr = g_xn2 + (size_t)t * CC;
    float sl = 0.f, sn = 0.f;
    for (int c = lane; c < CC; c += 32) {
        float xv = xr[c];
        sl += xv * Wr[c * EE + e];
        sn += xv * Wn[c * EE + e];
    }
#pragma unroll
    for (int o = 16; o > 0; o >>= 1) {
        sl += __shfl_xor_sync(0xffffffffu, sl, o);
        sn += __shfl_xor_sync(0xffffffffu, sn, o);
    }
    __shared__ float s_noisy[EE];
    if (lane == 0) {
        float lg = sl + br[e];
        float nl = sn + bn[e];
        float sp = (nl > 20.f) ? nl : log1pf(expf(nl));
        s_noisy[e] = lg + noise[(size_t)t * EE + e] * sp;
    }
    __syncthreads();
    if (tid == 0) {
        float n[EE];
#pragma unroll
        for (int i = 0; i < EE; i++) n[i] = s_noisy[i];
        int i1 = 0;
        for (int i = 1; i < EE; i++) if (n[i] > n[i1]) i1 = i;
        int i2 = -1;
        for (int i = 0; i < EE; i++) {
            if (i == i1) continue;
            if (i2 < 0 || n[i] > n[i2]) i2 = i;
        }
        float mx = fmaxf(n[i1], n[i2]);
        float e1 = __expf(n[i1] - mx), e2 = __expf(n[i2] - mx);
        float inv = 1.f / (e1 + e2);
#pragma unroll
        for (int i = 0; i < EE; i++) g_gate[(size_t)t * EE + i] = 0.f;
        g_gate[(size_t)t * EE + i1] = e1 * inv;
        g_gate[(size_t)t * EE + i2] = e2 * inv;
    }
}

// ---------------- compact lists + offsets + per-token slots (deterministic) ----------------
__global__ void build_lists() {
    int e = threadIdx.x >> 5, lane = threadIdx.x & 31;
    __shared__ int scnt[EE], soff[EE];
    // pass 1: counts
    int cnt = 0;
    for (int base = 0; base < TT; base += 32) {
        float gv = g_gate[(size_t)(base + lane) * EE + e];
        cnt += __popc(__ballot_sync(0xffffffffu, gv > 0.f));
    }
    if (lane == 0) scnt[e] = cnt;
    __syncthreads();
    if (threadIdx.x == 0) {
        int s = 0;
        for (int i = 0; i < EE; i++) { soff[i] = s; s += scnt[i]; }
    }
    __syncthreads();
    int off = soff[e];
    if (lane == 0) { g_count[e] = scnt[e]; g_off[e] = off; }
    // pass 2: fill compact arrays + inverse slots
    cnt = 0;
    for (int base = 0; base < TT; base += 32) {
        int t = base + lane;
        float gv = g_gate[(size_t)t * EE + e];
        unsigned m = __ballot_sync(0xffffffffu, gv > 0.f);
        if (gv > 0.f) {
            int pos = cnt + __popc(m & ((1u << lane) - 1u));
            int slot = off + pos;
            g_ctok [slot] = t;
            g_cgate[slot] = gv;
            int rank = 0;
#pragma unroll
            for (int e2 = 0; e2 < EE; e2++)
                if (e2 < e && g_gate[(size_t)t * EE + e2] > 0.f) rank++;
            g_slot[t * 2 + rank] = slot;
        }
        cnt += __popc(m);
    }
}

// ---------------- MoE layer 1, batched (1xTF32, gathered A): grid (FF/64, 16, EE) ----------------
__global__ __launch_bounds__(256, 2) void moe1_all(const float* __restrict__ W1, const float* __restrict__ b1) {
    int e = blockIdx.z;
    int Ne = g_count[e];
    int m0 = blockIdx.y * 128;
    if (m0 >= Ne) return;
    int off = g_off[e];
    int n0 = blockIdx.x * 64;
    const float* B = W1 + (size_t)e * CC * FF;
    const float* bias = b1 + (size_t)e * FF;
    __shared__ unsigned As[128][AP];
    __shared__ unsigned Bs[32][BP];
    __shared__ int rows[128];
    int tid = threadIdx.x, lane = tid & 31, warp = tid >> 5;
    int wm = warp >> 1, wn = warp & 1, g = lane >> 2, t4 = lane & 3;
    if (tid < 128) rows[tid] = (m0 + tid < Ne) ? g_ctok[off + m0 + tid] : 0;
    __syncthreads();
    float acc[2][4][4] = {};
    for (int k0 = 0; k0 < CC; k0 += 32) {
        float4 av[4], bv[2];
#pragma unroll
        for (int i = 0; i < 4; i++) {
            int idx = tid + i * 256, r = idx >> 3, c4 = (idx & 7) * 4;
            av[i] = *(const float4*)(g_xn2 + (size_t)rows[r] * CC + k0 + c4);
        }
#pragma unroll
        for (int i = 0; i < 2; i++) {
            int idx = tid + i * 256, r = idx >> 4, c4 = (idx & 15) * 4;
            bv[i] = *(const float4*)(B + (size_t)(k0 + r) * FF + n0 + c4);
        }
        __syncthreads();
#pragma unroll
        for (int i = 0; i < 4; i++) {
            int idx = tid + i * 256, r = idx >> 3, c4 = (idx & 7) * 4;
            cvt4(&As[r][c4], av[i]);
        }
#pragma unroll
        for (int i = 0; i < 2; i++) {
            int idx = tid + i * 256, r = idx >> 4, c4 = (idx & 15) * 4;
            cvt4(&Bs[r][c4], bv[i]);
        }
        __syncthreads();
        MMA_CHUNK(As, Bs, acc, wm, wn, g, t4)
    }
#pragma unroll
    for (int mi = 0; mi < 2; mi++)
#pragma unroll
        for (int ni = 0; ni < 4; ni++) {
            int row = m0 + wm*32 + mi*16 + g;
            int col = n0 + wn*32 + ni*8 + 2*t4;
            float* c = acc[mi][ni];
            float2 bb = *(const float2*)(bias + col);
#pragma unroll
            for (int rr = 0; rr < 2; rr++) {
                int m = row + rr*8;
                if (m < Ne)
                    *(float2*)(g_h + (size_t)(off + m) * FF + col) =
                        make_float2(fmaxf(c[rr*2+0] + bb.x, 0.f),
                                    fmaxf(c[rr*2+1] + bb.y, 0.f));
            }
        }
}

// ---------------- MoE layer 2, batched (1xTF32): y[slot] = gate*(h@W2[e]+b2), grid (CC/64, 16, EE) ----------------
__global__ __launch_bounds__(256, 2) void moe2_all(const float* __restrict__ W2, const float* __restrict__ b2) {
    int e = blockIdx.z;
    int Ne = g_count[e];
    int m0 = blockIdx.y * 128;
    if (m0 >= Ne) return;
    int off = g_off[e];
    int n0 = blockIdx.x * 64;
    const float* B = W2 + (size_t)e * FF * CC;
    const float* bias = b2 + (size_t)e * CC;
    __shared__ unsigned As[128][AP];
    __shared__ unsigned Bs[32][BP];
    int tid = threadIdx.x, lane = tid & 31, warp = tid >> 5;
    int wm = warp >> 1, wn = warp & 1, g = lane >> 2, t4 = lane & 3;
    float acc[2][4][4] = {};
    for (int k0 = 0; k0 < FF; k0 += 32) {
        float4 av[4], bv[2];
#pragma unroll
        for (int i = 0; i < 4; i++) {
            int idx = tid + i * 256, r = idx >> 3, c4 = (idx & 7) * 4;
            av[i] = *(const float4*)(g_h + (size_t)(off + m0 + r) * FF + k0 + c4);
        }
#pragma unroll
        for (int i = 0; i < 2; i++) {
            int idx = tid + i * 256, r = idx >> 4, c4 = (idx & 15) * 4;
            bv[i] = *(const float4*)(B + (size_t)(k0 + r) * CC + n0 + c4);
        }
        __syncthreads();
#pragma unroll
        for (int i = 0; i < 4; i++) {
            int idx = tid + i * 256, r = idx >> 3, c4 = (idx & 7) * 4;
            cvt4(&As[r][c4], av[i]);
        }
#pragma unroll
        for (int i = 0; i < 2; i++) {
            int idx = tid + i * 256, r = idx >> 4, c4 = (idx & 15) * 4;
            cvt4(&Bs[r][c4], bv[i]);
        }
        __syncthreads();
        MMA_CHUNK(As, Bs, acc, wm, wn, g, t4)
    }
#pragma unroll
    for (int mi = 0; mi < 2; mi++)
#pragma unroll
        for (int ni = 0; ni < 4; ni++) {
            int row = m0 + wm*32 + mi*16 + g;
            int col = n0 + wn*32 + ni*8 + 2*t4;
            float* c = acc[mi][ni];
            float2 bb = *(const float2*)(bias + col);
#pragma unroll
            for (int rr = 0; rr < 2; rr++) {
                int m = row + rr*8;
                if (m < Ne) {
                    float gv = g_cgate[off + m];
                    *(float2*)(g_y + (size_t)(off + m) * CC + col) =
                        make_float2(gv * (c[rr*2+0] + bb.x),
                                    gv * (c[rr*2+1] + bb.y));
                }
            }
        }
}

// ---------------- final scatter-add: out[t] += y[slot0] + y[slot1] ----------------
__global__ void moe_add(float* __restrict__ out) {
    int t = blockIdx.x;
    int c = threadIdx.x * 4;
    int s0 = g_slot[t * 2], s1 = g_slot[t * 2 + 1];
    float4 a = *(const float4*)(g_y + (size_t)s0 * CC + c);
    float4 b = *(const float4*)(g_y + (size_t)s1 * CC + c);
    float4 o = *(float4*)(out + (size_t)t * CC + c);
    o.x += a.x + b.x; o.y += a.y + b.y;
    o.z += a.z + b.z; o.w += a.w + b.w;
    *(float4*)(out + (size_t)t * CC + c) = o;
}

// ---------------- host launcher ----------------
extern "C" void kernel_launch(void* const* d_in, const int* in_sizes, int n_in,
                              void* d_out, int out_size) {
    const float* x     = (const float*)d_in[0];
    const float* noise = (const float*)d_in[1];
    const float* ln1_g = (const float*)d_in[2];
    const float* ln1_b = (const float*)d_in[3];
    const float* ln2_g = (const float*)d_in[4];
    const float* ln2_b = (const float*)d_in[5];
    const float* Wq    = (const float*)d_in[6];
    const float* Wk    = (const float*)d_in[7];
    const float* Wv    = (const float*)d_in[8];
    const float* Wp    = (const float*)d_in[9];
    const float* bp    = (const float*)d_in[10];
    const float* Wr    = (const float*)d_in[11];
    const float* br    = (const float*)d_in[12];
    const float* Wn    = (const float*)d_in[13];
    const float* bn    = (const float*)d_in[14];
    const float* W1    = (const float*)d_in[15];
    const float* b1    = (const float*)d_in[16];
    const float* W2    = (const float*)d_in[17];
    const float* b2    = (const float*)d_in[18];
    float* out = (float*)d_out;

    // LN1
    ln_kernel<<<TT, 256>>>(x, ln1_g, ln1_b, 0);
    // QKV (3xTF32, single launch)
    qkv_all<<<dim3(TT / 128, 3 * HH), 256>>>(Wq, Wk, Wv);
    // attention (bf16 tensor-core flash, 3-term split)
    attn_bf<<<dim3(TT / 128, HH), 256>>>();
    // proj + residual -> out (3xTF32)
    proj_tc<<<dim3(CC / 64, TT / 128), 256>>>(Wp, bp, x, out);
    // LN2 on x1
    ln_kernel<<<TT, 256>>>(out, ln2_g, ln2_b, 1);
    // router + compact lists
    router_kernel<<<TT, 256>>>(Wr, br, Wn, bn, noise);
    build_lists<<<1, 256>>>();
    // MoE: batched single launches (1xTF32), then deterministic scatter-add
    moe1_all<<<dim3(FF / 64, 16, EE), 256>>>(W1, b1);
    moe2_all<<<dim3(CC / 64, 16, EE), 256>>>(W2, b2);
    moe_add<<<TT, 256>>>(out);
}